// round 1
// baseline (speedup 1.0000x reference)
#include <cuda_runtime.h>
#include <cuda_bf16.h>
#include <math.h>

// Problem constants
#define BATCH 32
#define NV    512
#define NQ    256
#define DMODEL 1024
#define D3    3072
#define NHEAD 8
#define DH    128

// ---------------------------------------------------------------------------
// Scratch (static device globals — allocation-free per harness rules)
// ---------------------------------------------------------------------------
__device__ float g_vmean[BATCH * DMODEL];
__device__ float g_qmean[BATCH * DMODEL];
__device__ float g_gate_v[BATCH * DMODEL];   // gv = 1 + sigmoid(q_mean @ w_q4v + b)  (multiplies v-side)
__device__ float g_gate_q[BATCH * DMODEL];   // gq = 1 + sigmoid(v_mean @ w_v4q + b)  (multiplies q-side)
__device__ float g_vtran[BATCH * NV * D3];   // gated relu(v @ w_vlin + b)
__device__ float g_qtran[BATCH * NQ * D3];
__device__ float g_vupd[BATCH * NV * DMODEL];
__device__ float g_qupd[BATCH * NQ * DMODEL];

// ---------------------------------------------------------------------------
// Row means:  out[b][d] = mean over nrows of x[b][n][d]
// ---------------------------------------------------------------------------
__global__ void mean_kernel(const float* __restrict__ x, float* __restrict__ out, int nrows) {
    int b = blockIdx.x;
    int d = blockIdx.y * 256 + threadIdx.x;
    const float* p = x + (size_t)b * nrows * DMODEL + d;
    float s0 = 0.f, s1 = 0.f, s2 = 0.f, s3 = 0.f;
    for (int n = 0; n < nrows; n += 4) {
        s0 += p[(size_t)(n + 0) * DMODEL];
        s1 += p[(size_t)(n + 1) * DMODEL];
        s2 += p[(size_t)(n + 2) * DMODEL];
        s3 += p[(size_t)(n + 3) * DMODEL];
    }
    out[b * DMODEL + d] = (s0 + s1 + s2 + s3) / (float)nrows;
}

// ---------------------------------------------------------------------------
// Gates: gate[b][d] = 1 + sigmoid(mean[b] . W[:,d] + bias[d])
// ---------------------------------------------------------------------------
__global__ void gate_kernel(const float* __restrict__ mean, const float* __restrict__ W,
                            const float* __restrict__ bias, float* __restrict__ gate) {
    __shared__ float sm[DMODEL];
    int b = blockIdx.x;
    int d = blockIdx.y * 256 + threadIdx.x;
    for (int i = threadIdx.x; i < DMODEL; i += 256) sm[i] = mean[b * DMODEL + i];
    __syncthreads();
    float acc = bias[d];
#pragma unroll 4
    for (int k = 0; k < DMODEL; k++) acc += sm[k] * W[(size_t)k * DMODEL + d];
    gate[b * DMODEL + d] = 1.0f + 1.0f / (1.0f + __expf(-acc));
}

// ---------------------------------------------------------------------------
// SGEMM 128x128 tile, 8x8 microtile, 256 threads.
//   C[M,N] = epilogue( (A [+A2]) @ W + bias )
//   RELU: relu.  GATE: multiply by gate[b*1024 + (col & 1023)], b = row/rows_per_batch.
// All of M, N multiples of 128; K multiple of 16.
// ---------------------------------------------------------------------------
template <bool GATE>
__global__ __launch_bounds__(256)
void sgemm128(const float* __restrict__ A, const float* __restrict__ A2,
              const float* __restrict__ W, const float* __restrict__ bias,
              const float* __restrict__ gate, float* __restrict__ C,
              int M, int N, int K, int rows_per_batch) {
    constexpr int BM = 128, BN = 128, BK = 16, TM = 8, TN = 8;
    __shared__ float As[BK][BM];
    __shared__ float Bs[BK][BN];

    const int tid = threadIdx.x;
    const int tx = tid % 16;   // n dir
    const int ty = tid / 16;   // m dir
    const int row0 = blockIdx.y * BM;
    const int col0 = blockIdx.x * BN;

    // A tile loader coords: each thread loads 2 float4 (rows a_r, a_r+64)
    const int a_r = tid / 4;
    const int a_c = (tid % 4) * 4;
    // B tile loader coords: each thread loads 2 float4 (k-rows b_r, b_r+8)
    const int b_r = tid / 32;
    const int b_c = (tid % 32) * 4;

    float acc[TM][TN];
#pragma unroll
    for (int i = 0; i < TM; i++)
#pragma unroll
        for (int j = 0; j < TN; j++) acc[i][j] = 0.f;

    for (int k0 = 0; k0 < K; k0 += BK) {
#pragma unroll
        for (int i = 0; i < 2; i++) {
            int r = a_r + i * 64;
            float4 v = *(const float4*)(A + (size_t)(row0 + r) * K + k0 + a_c);
            if (A2) {
                float4 w = *(const float4*)(A2 + (size_t)(row0 + r) * K + k0 + a_c);
                v.x += w.x; v.y += w.y; v.z += w.z; v.w += w.w;
            }
            As[a_c + 0][r] = v.x;
            As[a_c + 1][r] = v.y;
            As[a_c + 2][r] = v.z;
            As[a_c + 3][r] = v.w;
        }
#pragma unroll
        for (int i = 0; i < 2; i++) {
            int r = b_r + i * 8;
            *(float4*)&Bs[r][b_c] = *(const float4*)(W + (size_t)(k0 + r) * N + col0 + b_c);
        }
        __syncthreads();

#pragma unroll
        for (int kk = 0; kk < BK; kk++) {
            float a[TM], bb[TN];
#pragma unroll
            for (int i = 0; i < TM; i++) a[i] = As[kk][ty * TM + i];
#pragma unroll
            for (int j = 0; j < TN; j++) bb[j] = Bs[kk][tx * TN + j];
#pragma unroll
            for (int i = 0; i < TM; i++)
#pragma unroll
                for (int j = 0; j < TN; j++) acc[i][j] += a[i] * bb[j];
        }
        __syncthreads();
    }

    const int b_idx = GATE ? (row0 / rows_per_batch) : 0;
#pragma unroll
    for (int i = 0; i < TM; i++) {
        int r = row0 + ty * TM + i;
#pragma unroll
        for (int j = 0; j < TN; j += 4) {
            int c = col0 + tx * TN + j;
            float4 o;
            o.x = fmaxf(acc[i][j + 0] + bias[c + 0], 0.f);
            o.y = fmaxf(acc[i][j + 1] + bias[c + 1], 0.f);
            o.z = fmaxf(acc[i][j + 2] + bias[c + 2], 0.f);
            o.w = fmaxf(acc[i][j + 3] + bias[c + 3], 0.f);
            if (GATE) {
                o.x *= gate[b_idx * DMODEL + ((c + 0) & (DMODEL - 1))];
                o.y *= gate[b_idx * DMODEL + ((c + 1) & (DMODEL - 1))];
                o.z *= gate[b_idx * DMODEL + ((c + 2) & (DMODEL - 1))];
                o.w *= gate[b_idx * DMODEL + ((c + 3) & (DMODEL - 1))];
            }
            *(float4*)&C[(size_t)r * N + c] = o;
        }
    }
}

// ---------------------------------------------------------------------------
// Multi-head self-attention on the gated tran buffer.
//   tran: [B, NROWS, 3072]  (key | query | val, each [.,.,8 heads x 128])
//   upd : [B, NROWS, 1024]  out[b,n,h*128+d]
// Block: 128 threads, handles (b, h, 16-query tile). Full logits row in SMEM.
// ---------------------------------------------------------------------------
template <int NK, int NROWS>
__global__ __launch_bounds__(128)
void attn_kernel(const float* __restrict__ tran, float* __restrict__ upd) {
    constexpr int TQ = 16, TK = 64;
    constexpr int QS = DH + 4;   // 132, padded stride
    constexpr int SS = NK + 4;   // padded logits stride
    extern __shared__ float smf[];
    float* Qs   = smf;                 // TQ * QS
    float* KV   = Qs + TQ * QS;        // TK * QS
    float* S    = KV + TK * QS;        // TQ * SS
    float* rinv = S + TQ * SS;         // TQ

    const int tid = threadIdx.x;
    const int qt = blockIdx.x, h = blockIdx.y, b = blockIdx.z;
    const size_t base = (size_t)b * NROWS * D3 + (size_t)h * DH;
    const int q0 = qt * TQ;

    // load Q tile (query part: +1024)
    for (int idx = tid; idx < TQ * DH; idx += 128) {
        int qi = idx / DH, d = idx % DH;
        Qs[qi * QS + d] = tran[base + (size_t)(q0 + qi) * D3 + DMODEL + d];
    }

    const int sq = tid >> 3;      // query row within tile (0..15)
    const int sk = tid & 7;       // key lane (keys sk, sk+8, ..., sk+56 within tile)

    // ---- logits S = (Q . K^T) / sqrt(DH) ----
    for (int kt = 0; kt < NK; kt += TK) {
        __syncthreads();
        for (int idx = tid; idx < TK * DH; idx += 128) {
            int r = idx / DH, d = idx % DH;
            KV[r * QS + d] = tran[base + (size_t)(kt + r) * D3 + d];   // key part: +0
        }
        __syncthreads();
        float acc[8];
#pragma unroll
        for (int j = 0; j < 8; j++) acc[j] = 0.f;
        for (int d = 0; d < DH; d += 4) {
            float4 qv = *(float4*)&Qs[sq * QS + d];
#pragma unroll
            for (int j = 0; j < 8; j++) {
                float4 kv = *(float4*)&KV[(sk + 8 * j) * QS + d];
                acc[j] += qv.x * kv.x + qv.y * kv.y + qv.z * kv.z + qv.w * kv.w;
            }
        }
        const float scale = 0.08838834764831845f;  // 1/sqrt(128)
#pragma unroll
        for (int j = 0; j < 8; j++) S[sq * SS + kt + sk + 8 * j] = acc[j] * scale;
    }
    __syncthreads();

    // ---- softmax (unnormalized exp stored; 1/sum saved per row) ----
    {
        float m = -1e30f;
        for (int c = sk; c < NK; c += 8) m = fmaxf(m, S[sq * SS + c]);
        m = fmaxf(m, __shfl_xor_sync(0xffffffffu, m, 1));
        m = fmaxf(m, __shfl_xor_sync(0xffffffffu, m, 2));
        m = fmaxf(m, __shfl_xor_sync(0xffffffffu, m, 4));
        float s = 0.f;
        for (int c = sk; c < NK; c += 8) {
            float e = __expf(S[sq * SS + c] - m);
            S[sq * SS + c] = e;
            s += e;
        }
        s += __shfl_xor_sync(0xffffffffu, s, 1);
        s += __shfl_xor_sync(0xffffffffu, s, 2);
        s += __shfl_xor_sync(0xffffffffu, s, 4);
        if (sk == 0) rinv[sq] = 1.0f / s;
    }

    // ---- O = P @ V ----
    const int dsub = sk * 16;   // each thread owns 16 contiguous d-columns
    float o[16];
#pragma unroll
    for (int j = 0; j < 16; j++) o[j] = 0.f;
    for (int kt = 0; kt < NK; kt += TK) {
        __syncthreads();
        for (int idx = tid; idx < TK * DH; idx += 128) {
            int r = idx / DH, d = idx % DH;
            KV[r * QS + d] = tran[base + (size_t)(kt + r) * D3 + 2 * DMODEL + d];  // val part
        }
        __syncthreads();
        for (int k = 0; k < TK; k++) {
            float p = S[sq * SS + kt + k];
#pragma unroll
            for (int j4 = 0; j4 < 16; j4 += 4) {
                float4 vv = *(float4*)&KV[k * QS + dsub + j4];
                o[j4 + 0] += p * vv.x;
                o[j4 + 1] += p * vv.y;
                o[j4 + 2] += p * vv.z;
                o[j4 + 3] += p * vv.w;
            }
        }
    }
    const float inv = rinv[sq];
    float* dst = upd + (size_t)(b * NROWS + q0 + sq) * DMODEL + h * DH + dsub;
#pragma unroll
    for (int j4 = 0; j4 < 16; j4 += 4) {
        float4 ov = {o[j4] * inv, o[j4 + 1] * inv, o[j4 + 2] * inv, o[j4 + 3] * inv};
        *(float4*)&dst[j4] = ov;
    }
}

// ---------------------------------------------------------------------------
// launch
// ---------------------------------------------------------------------------
extern "C" void kernel_launch(void* const* d_in, const int* in_sizes, int n_in,
                              void* d_out, int out_size) {
    const float* v      = (const float*)d_in[0];
    const float* q      = (const float*)d_in[1];
    const float* w_v4q  = (const float*)d_in[2];
    const float* b_v4q  = (const float*)d_in[3];
    const float* w_q4v  = (const float*)d_in[4];
    const float* b_q4v  = (const float*)d_in[5];
    const float* w_vlin = (const float*)d_in[6];
    const float* b_vlin = (const float*)d_in[7];
    const float* w_qlin = (const float*)d_in[8];
    const float* b_qlin = (const float*)d_in[9];
    const float* w_vout = (const float*)d_in[10];
    const float* b_vout = (const float*)d_in[11];
    const float* w_qout = (const float*)d_in[12];
    const float* b_qout = (const float*)d_in[13];

    float* out_v = (float*)d_out;
    float* out_q = out_v + (size_t)BATCH * NV * DMODEL;

    float *p_vmean, *p_qmean, *p_gv, *p_gq, *p_vtran, *p_qtran, *p_vupd, *p_qupd;
    cudaGetSymbolAddress((void**)&p_vmean, g_vmean);
    cudaGetSymbolAddress((void**)&p_qmean, g_qmean);
    cudaGetSymbolAddress((void**)&p_gv,    g_gate_v);
    cudaGetSymbolAddress((void**)&p_gq,    g_gate_q);
    cudaGetSymbolAddress((void**)&p_vtran, g_vtran);
    cudaGetSymbolAddress((void**)&p_qtran, g_qtran);
    cudaGetSymbolAddress((void**)&p_vupd,  g_vupd);
    cudaGetSymbolAddress((void**)&p_qupd,  g_qupd);

    const int smemV = (16 * 132 + 64 * 132 + 16 * (512 + 4) + 16) * (int)sizeof(float);
    const int smemQ = (16 * 132 + 64 * 132 + 16 * (256 + 4) + 16) * (int)sizeof(float);
    cudaFuncSetAttribute(attn_kernel<512, NV>, cudaFuncAttributeMaxDynamicSharedMemorySize, smemV);
    cudaFuncSetAttribute(attn_kernel<256, NQ>, cudaFuncAttributeMaxDynamicSharedMemorySize, smemQ);

    // means
    mean_kernel<<<dim3(BATCH, 4), 256>>>(v, p_vmean, NV);
    mean_kernel<<<dim3(BATCH, 4), 256>>>(q, p_qmean, NQ);
    // gates: gq (for q-side) from v_mean@w_v4q ; gv (for v-side) from q_mean@w_q4v
    gate_kernel<<<dim3(BATCH, 4), 256>>>(p_vmean, w_v4q, b_v4q, p_gq);
    gate_kernel<<<dim3(BATCH, 4), 256>>>(p_qmean, w_q4v, b_q4v, p_gv);
    // gated tran projections
    sgemm128<true><<<dim3(D3 / 128, BATCH * NV / 128), 256>>>(
        v, nullptr, w_vlin, b_vlin, p_gv, p_vtran, BATCH * NV, D3, DMODEL, NV);
    sgemm128<true><<<dim3(D3 / 128, BATCH * NQ / 128), 256>>>(
        q, nullptr, w_qlin, b_qlin, p_gq, p_qtran, BATCH * NQ, D3, DMODEL, NQ);
    // attention
    attn_kernel<512, NV><<<dim3(NV / 16, NHEAD, BATCH), 128, smemV>>>(p_vtran, p_vupd);
    attn_kernel<256, NQ><<<dim3(NQ / 16, NHEAD, BATCH), 128, smemQ>>>(p_qtran, p_qupd);
    // output projections with fused residual add + relu
    sgemm128<false><<<dim3(DMODEL / 128, BATCH * NV / 128), 256>>>(
        v, p_vupd, w_vout, b_vout, nullptr, out_v, BATCH * NV, DMODEL, DMODEL, NV);
    sgemm128<false><<<dim3(DMODEL / 128, BATCH * NQ / 128), 256>>>(
        q, p_qupd, w_qout, b_qout, nullptr, out_q, BATCH * NQ, DMODEL, DMODEL, NQ);
}

// round 2
// speedup vs baseline: 1.0572x; 1.0572x over previous
#include <cuda_runtime.h>
#include <cuda_bf16.h>
#include <math.h>
#include <stdint.h>

// Problem constants
#define BATCH 32
#define NV    512
#define NQ    256
#define DMODEL 1024
#define D3    3072
#define NHEAD 8
#define DH    128

// ---------------------------------------------------------------------------
// Scratch (static device globals — allocation-free per harness rules)
// ---------------------------------------------------------------------------
__device__ float g_vmean[BATCH * DMODEL];
__device__ float g_qmean[BATCH * DMODEL];
__device__ float g_gate_v[BATCH * DMODEL];   // gv (multiplies v-side tran)
__device__ float g_gate_q[BATCH * DMODEL];   // gq (multiplies q-side tran)
__device__ float g_vtran[BATCH * NV * D3];
__device__ float g_qtran[BATCH * NQ * D3];
__device__ float g_vupd[BATCH * NV * DMODEL];
__device__ float g_qupd[BATCH * NQ * DMODEL];

// ---------------------------------------------------------------------------
// tf32 split helpers
// ---------------------------------------------------------------------------
__device__ __forceinline__ void split_tf32(float x, float& hi, float& lo) {
    uint32_t h;
    asm("cvt.rna.tf32.f32 %0, %1;" : "=r"(h) : "f"(x));
    hi = __uint_as_float(h);
    float r = x - hi;
    uint32_t l;
    asm("cvt.rna.tf32.f32 %0, %1;" : "=r"(l) : "f"(r));
    lo = __uint_as_float(l);
}

__device__ __forceinline__ void mma_tf32(float* c, const uint32_t* a, const uint32_t* b) {
    asm volatile(
        "mma.sync.aligned.m16n8k8.row.col.f32.tf32.tf32.f32 "
        "{%0,%1,%2,%3}, {%4,%5,%6,%7}, {%8,%9}, {%0,%1,%2,%3};\n"
        : "+f"(c[0]), "+f"(c[1]), "+f"(c[2]), "+f"(c[3])
        : "r"(a[0]), "r"(a[1]), "r"(a[2]), "r"(a[3]), "r"(b[0]), "r"(b[1]));
}

// ---------------------------------------------------------------------------
// Row means
// ---------------------------------------------------------------------------
__global__ void mean_kernel(const float* __restrict__ x, float* __restrict__ out, int nrows) {
    int b = blockIdx.x;
    int d = blockIdx.y * 256 + threadIdx.x;
    const float* p = x + (size_t)b * nrows * DMODEL + d;
    float s0 = 0.f, s1 = 0.f, s2 = 0.f, s3 = 0.f;
    for (int n = 0; n < nrows; n += 4) {
        s0 += p[(size_t)(n + 0) * DMODEL];
        s1 += p[(size_t)(n + 1) * DMODEL];
        s2 += p[(size_t)(n + 2) * DMODEL];
        s3 += p[(size_t)(n + 3) * DMODEL];
    }
    out[b * DMODEL + d] = (s0 + s1 + s2 + s3) / (float)nrows;
}

// ---------------------------------------------------------------------------
// Gates: gate[b][d] = 1 + sigmoid(mean[b] . W[:,d] + bias[d])
// 128 threads/block, grid (B, 8); 4 accumulators to break the FFMA chain.
// ---------------------------------------------------------------------------
__global__ __launch_bounds__(128)
void gate_kernel(const float* __restrict__ mean, const float* __restrict__ W,
                 const float* __restrict__ bias, float* __restrict__ gate) {
    __shared__ float sm[DMODEL];
    int b = blockIdx.x;
    int d = blockIdx.y * 128 + threadIdx.x;
    for (int i = threadIdx.x; i < DMODEL; i += 128) sm[i] = mean[b * DMODEL + i];
    __syncthreads();
    float a0 = 0.f, a1 = 0.f, a2 = 0.f, a3 = 0.f;
#pragma unroll 4
    for (int k = 0; k < DMODEL; k += 4) {
        a0 += sm[k + 0] * __ldg(&W[(size_t)(k + 0) * DMODEL + d]);
        a1 += sm[k + 1] * __ldg(&W[(size_t)(k + 1) * DMODEL + d]);
        a2 += sm[k + 2] * __ldg(&W[(size_t)(k + 2) * DMODEL + d]);
        a3 += sm[k + 3] * __ldg(&W[(size_t)(k + 3) * DMODEL + d]);
    }
    float acc = (a0 + a1) + (a2 + a3) + bias[d];
    gate[b * DMODEL + d] = 1.0f + 1.0f / (1.0f + __expf(-acc));
}

// ---------------------------------------------------------------------------
// 3xTF32 tensor-core GEMM, 128x128 block tile, BK=16, 256 threads (8 warps),
// warp tile 32x64 (2x8 m16n8k8 tiles).
//   C = epilogue( (A [+A2]) @ W + bias ),  epilogue = relu [* gate]
// M, N multiples of 128; K multiple of 16.
// ---------------------------------------------------------------------------
template <bool GATE>
__global__ __launch_bounds__(256)
void mma_gemm(const float* __restrict__ A, const float* __restrict__ A2,
              const float* __restrict__ W, const float* __restrict__ bias,
              const float* __restrict__ gate, float* __restrict__ C,
              int M, int N, int K, int rows_per_batch) {
    constexpr int BM = 128, BN = 128, BK = 16;
    constexpr int AS = BM + 8;   // 136: stride 8 mod 32 -> conflict-free frag loads
    constexpr int BS = BN + 8;
    __shared__ __align__(16) float Ah[BK][AS];
    __shared__ __align__(16) float Al[BK][AS];
    __shared__ __align__(16) float Bh[BK][BS];
    __shared__ __align__(16) float Bl[BK][BS];

    const int tid = threadIdx.x;
    const int warp = tid >> 5;
    const int lane = tid & 31;
    const int gid = lane >> 2;    // groupID (0..7)
    const int tig = lane & 3;     // threadID in group (0..3)
    const int wm = warp & 3;      // warp m index (0..3) -> 32 rows each
    const int wn = warp >> 2;     // warp n index (0..1) -> 64 cols each

    const int row0 = blockIdx.y * BM;
    const int col0 = blockIdx.x * BN;

    // A loader: thread handles rows a_r, a_r+64 at k-cols a_c..a_c+3
    const int a_r = tid >> 2;
    const int a_c = (tid & 3) * 4;
    // B loader: thread handles k-rows b_r, b_r+8 at n-cols b_c..b_c+3
    const int b_r = tid >> 5;
    const int b_c = (tid & 31) * 4;

    float acc[2][8][4];
#pragma unroll
    for (int i = 0; i < 2; i++)
#pragma unroll
        for (int j = 0; j < 8; j++)
#pragma unroll
            for (int t = 0; t < 4; t++) acc[i][j][t] = 0.f;

    for (int k0 = 0; k0 < K; k0 += BK) {
        // ---- load + split A tile ----
#pragma unroll
        for (int i = 0; i < 2; i++) {
            int r = a_r + i * 64;
            float4 v = *(const float4*)(A + (size_t)(row0 + r) * K + k0 + a_c);
            if (A2) {
                float4 w = *(const float4*)(A2 + (size_t)(row0 + r) * K + k0 + a_c);
                v.x += w.x; v.y += w.y; v.z += w.z; v.w += w.w;
            }
            float h, l;
            split_tf32(v.x, h, l); Ah[a_c + 0][r] = h; Al[a_c + 0][r] = l;
            split_tf32(v.y, h, l); Ah[a_c + 1][r] = h; Al[a_c + 1][r] = l;
            split_tf32(v.z, h, l); Ah[a_c + 2][r] = h; Al[a_c + 2][r] = l;
            split_tf32(v.w, h, l); Ah[a_c + 3][r] = h; Al[a_c + 3][r] = l;
        }
        // ---- load + split B tile ----
#pragma unroll
        for (int i = 0; i < 2; i++) {
            int r = b_r + i * 8;
            float4 v = *(const float4*)(W + (size_t)(k0 + r) * N + col0 + b_c);
            float4 hv, lv;
            split_tf32(v.x, hv.x, lv.x);
            split_tf32(v.y, hv.y, lv.y);
            split_tf32(v.z, hv.z, lv.z);
            split_tf32(v.w, hv.w, lv.w);
            *(float4*)&Bh[r][b_c] = hv;
            *(float4*)&Bl[r][b_c] = lv;
        }
        __syncthreads();

#pragma unroll
        for (int ks = 0; ks < 2; ks++) {
            const int k = ks * 8;
            uint32_t ah[2][4], al[2][4];
#pragma unroll
            for (int mi = 0; mi < 2; mi++) {
                const int m = wm * 32 + mi * 16;
                ah[mi][0] = __float_as_uint(Ah[k + tig]    [m + gid]);
                ah[mi][1] = __float_as_uint(Ah[k + tig]    [m + gid + 8]);
                ah[mi][2] = __float_as_uint(Ah[k + tig + 4][m + gid]);
                ah[mi][3] = __float_as_uint(Ah[k + tig + 4][m + gid + 8]);
                al[mi][0] = __float_as_uint(Al[k + tig]    [m + gid]);
                al[mi][1] = __float_as_uint(Al[k + tig]    [m + gid + 8]);
                al[mi][2] = __float_as_uint(Al[k + tig + 4][m + gid]);
                al[mi][3] = __float_as_uint(Al[k + tig + 4][m + gid + 8]);
            }
            uint32_t bh[8][2], bl[8][2];
#pragma unroll
            for (int ni = 0; ni < 8; ni++) {
                const int n = wn * 64 + ni * 8;
                bh[ni][0] = __float_as_uint(Bh[k + tig]    [n + gid]);
                bh[ni][1] = __float_as_uint(Bh[k + tig + 4][n + gid]);
                bl[ni][0] = __float_as_uint(Bl[k + tig]    [n + gid]);
                bl[ni][1] = __float_as_uint(Bl[k + tig + 4][n + gid]);
            }
#pragma unroll
            for (int mi = 0; mi < 2; mi++)
#pragma unroll
                for (int ni = 0; ni < 8; ni++) {
                    mma_tf32(acc[mi][ni], ah[mi], bh[ni]);
                    mma_tf32(acc[mi][ni], al[mi], bh[ni]);
                    mma_tf32(acc[mi][ni], ah[mi], bl[ni]);
                }
        }
        __syncthreads();
    }

    // ---- epilogue ----
    const int b_idx = GATE ? (row0 / rows_per_batch) : 0;
#pragma unroll
    for (int mi = 0; mi < 2; mi++) {
        int ra = row0 + wm * 32 + mi * 16 + gid;
#pragma unroll
        for (int ni = 0; ni < 8; ni++) {
            int c = col0 + wn * 64 + ni * 8 + tig * 2;
            float g0 = 1.f, g1 = 1.f;
            if (GATE) {
                g0 = gate[b_idx * DMODEL + (c & (DMODEL - 1))];
                g1 = gate[b_idx * DMODEL + ((c + 1) & (DMODEL - 1))];
            }
            float bz0 = bias[c], bz1 = bias[c + 1];
            float2 o0, o1;
            o0.x = fmaxf(acc[mi][ni][0] + bz0, 0.f) * g0;
            o0.y = fmaxf(acc[mi][ni][1] + bz1, 0.f) * g1;
            o1.x = fmaxf(acc[mi][ni][2] + bz0, 0.f) * g0;
            o1.y = fmaxf(acc[mi][ni][3] + bz1, 0.f) * g1;
            *(float2*)&C[(size_t)ra * N + c] = o0;
            *(float2*)&C[(size_t)(ra + 8) * N + c] = o1;
        }
    }
}

// ---------------------------------------------------------------------------
// Multi-head self-attention on the gated tran buffer (fp32 scalar).
// ---------------------------------------------------------------------------
template <int NK, int NROWS>
__global__ __launch_bounds__(128)
void attn_kernel(const float* __restrict__ tran, float* __restrict__ upd) {
    constexpr int TQ = 16, TK = 64;
    constexpr int QS = DH + 4;
    constexpr int SS = NK + 4;
    extern __shared__ float smf[];
    float* Qs   = smf;
    float* KV   = Qs + TQ * QS;
    float* S    = KV + TK * QS;
    float* rinv = S + TQ * SS;

    const int tid = threadIdx.x;
    const int qt = blockIdx.x, h = blockIdx.y, b = blockIdx.z;
    const size_t base = (size_t)b * NROWS * D3 + (size_t)h * DH;
    const int q0 = qt * TQ;

    for (int idx = tid; idx < TQ * DH; idx += 128) {
        int qi = idx / DH, d = idx % DH;
        Qs[qi * QS + d] = tran[base + (size_t)(q0 + qi) * D3 + DMODEL + d];
    }

    const int sq = tid >> 3;
    const int sk = tid & 7;

    for (int kt = 0; kt < NK; kt += TK) {
        __syncthreads();
        for (int idx = tid; idx < TK * DH; idx += 128) {
            int r = idx / DH, d = idx % DH;
            KV[r * QS + d] = tran[base + (size_t)(kt + r) * D3 + d];
        }
        __syncthreads();
        float acc[8];
#pragma unroll
        for (int j = 0; j < 8; j++) acc[j] = 0.f;
        for (int d = 0; d < DH; d += 4) {
            float4 qv = *(float4*)&Qs[sq * QS + d];
#pragma unroll
            for (int j = 0; j < 8; j++) {
                float4 kv = *(float4*)&KV[(sk + 8 * j) * QS + d];
                acc[j] += qv.x * kv.x + qv.y * kv.y + qv.z * kv.z + qv.w * kv.w;
            }
        }
        const float scale = 0.08838834764831845f;
#pragma unroll
        for (int j = 0; j < 8; j++) S[sq * SS + kt + sk + 8 * j] = acc[j] * scale;
    }
    __syncthreads();

    {
        float m = -1e30f;
        for (int c = sk; c < NK; c += 8) m = fmaxf(m, S[sq * SS + c]);
        m = fmaxf(m, __shfl_xor_sync(0xffffffffu, m, 1));
        m = fmaxf(m, __shfl_xor_sync(0xffffffffu, m, 2));
        m = fmaxf(m, __shfl_xor_sync(0xffffffffu, m, 4));
        float s = 0.f;
        for (int c = sk; c < NK; c += 8) {
            float e = __expf(S[sq * SS + c] - m);
            S[sq * SS + c] = e;
            s += e;
        }
        s += __shfl_xor_sync(0xffffffffu, s, 1);
        s += __shfl_xor_sync(0xffffffffu, s, 2);
        s += __shfl_xor_sync(0xffffffffu, s, 4);
        if (sk == 0) rinv[sq] = 1.0f / s;
    }

    const int dsub = sk * 16;
    float o[16];
#pragma unroll
    for (int j = 0; j < 16; j++) o[j] = 0.f;
    for (int kt = 0; kt < NK; kt += TK) {
        __syncthreads();
        for (int idx = tid; idx < TK * DH; idx += 128) {
            int r = idx / DH, d = idx % DH;
            KV[r * QS + d] = tran[base + (size_t)(kt + r) * D3 + 2 * DMODEL + d];
        }
        __syncthreads();
        for (int k = 0; k < TK; k++) {
            float p = S[sq * SS + kt + k];
#pragma unroll
            for (int j4 = 0; j4 < 16; j4 += 4) {
                float4 vv = *(float4*)&KV[k * QS + dsub + j4];
                o[j4 + 0] += p * vv.x;
                o[j4 + 1] += p * vv.y;
                o[j4 + 2] += p * vv.z;
                o[j4 + 3] += p * vv.w;
            }
        }
    }
    const float inv = rinv[sq];
    float* dst = upd + (size_t)(b * NROWS + q0 + sq) * DMODEL + h * DH + dsub;
#pragma unroll
    for (int j4 = 0; j4 < 16; j4 += 4) {
        float4 ov = {o[j4] * inv, o[j4 + 1] * inv, o[j4 + 2] * inv, o[j4 + 3] * inv};
        *(float4*)&dst[j4] = ov;
    }
}

// ---------------------------------------------------------------------------
// launch
// ---------------------------------------------------------------------------
extern "C" void kernel_launch(void* const* d_in, const int* in_sizes, int n_in,
                              void* d_out, int out_size) {
    const float* v      = (const float*)d_in[0];
    const float* q      = (const float*)d_in[1];
    const float* w_v4q  = (const float*)d_in[2];
    const float* b_v4q  = (const float*)d_in[3];
    const float* w_q4v  = (const float*)d_in[4];
    const float* b_q4v  = (const float*)d_in[5];
    const float* w_vlin = (const float*)d_in[6];
    const float* b_vlin = (const float*)d_in[7];
    const float* w_qlin = (const float*)d_in[8];
    const float* b_qlin = (const float*)d_in[9];
    const float* w_vout = (const float*)d_in[10];
    const float* b_vout = (const float*)d_in[11];
    const float* w_qout = (const float*)d_in[12];
    const float* b_qout = (const float*)d_in[13];

    float* out_v = (float*)d_out;
    float* out_q = out_v + (size_t)BATCH * NV * DMODEL;

    float *p_vmean, *p_qmean, *p_gv, *p_gq, *p_vtran, *p_qtran, *p_vupd, *p_qupd;
    cudaGetSymbolAddress((void**)&p_vmean, g_vmean);
    cudaGetSymbolAddress((void**)&p_qmean, g_qmean);
    cudaGetSymbolAddress((void**)&p_gv,    g_gate_v);
    cudaGetSymbolAddress((void**)&p_gq,    g_gate_q);
    cudaGetSymbolAddress((void**)&p_vtran, g_vtran);
    cudaGetSymbolAddress((void**)&p_qtran, g_qtran);
    cudaGetSymbolAddress((void**)&p_vupd,  g_vupd);
    cudaGetSymbolAddress((void**)&p_qupd,  g_qupd);

    const int smemV = (16 * 132 + 64 * 132 + 16 * (512 + 4) + 16) * (int)sizeof(float);
    const int smemQ = (16 * 132 + 64 * 132 + 16 * (256 + 4) + 16) * (int)sizeof(float);
    cudaFuncSetAttribute(attn_kernel<512, NV>, cudaFuncAttributeMaxDynamicSharedMemorySize, smemV);
    cudaFuncSetAttribute(attn_kernel<256, NQ>, cudaFuncAttributeMaxDynamicSharedMemorySize, smemQ);

    // means
    mean_kernel<<<dim3(BATCH, 4), 256>>>(v, p_vmean, NV);
    mean_kernel<<<dim3(BATCH, 4), 256>>>(q, p_qmean, NQ);
    // gates: gq from v_mean@w_v4q ; gv from q_mean@w_q4v
    gate_kernel<<<dim3(BATCH, 8), 128>>>(p_vmean, w_v4q, b_v4q, p_gq);
    gate_kernel<<<dim3(BATCH, 8), 128>>>(p_qmean, w_q4v, b_q4v, p_gv);
    // gated tran projections (tensor core)
    mma_gemm<true><<<dim3(D3 / 128, BATCH * NV / 128), 256>>>(
        v, nullptr, w_vlin, b_vlin, p_gv, p_vtran, BATCH * NV, D3, DMODEL, NV);
    mma_gemm<true><<<dim3(D3 / 128, BATCH * NQ / 128), 256>>>(
        q, nullptr, w_qlin, b_qlin, p_gq, p_qtran, BATCH * NQ, D3, DMODEL, NQ);
    // attention
    attn_kernel<512, NV><<<dim3(NV / 16, NHEAD, BATCH), 128, smemV>>>(p_vtran, p_vupd);
    attn_kernel<256, NQ><<<dim3(NQ / 16, NHEAD, BATCH), 128, smemQ>>>(p_qtran, p_qupd);
    // output projections with fused residual add + relu (tensor core)
    mma_gemm<false><<<dim3(DMODEL / 128, BATCH * NV / 128), 256>>>(
        v, p_vupd, w_vout, b_vout, nullptr, out_v, BATCH * NV, DMODEL, DMODEL, NV);
    mma_gemm<false><<<dim3(DMODEL / 128, BATCH * NQ / 128), 256>>>(
        q, p_qupd, w_qout, b_qout, nullptr, out_q, BATCH * NQ, DMODEL, DMODEL, NQ);
}

// round 5
// speedup vs baseline: 1.3802x; 1.3056x over previous
#include <cuda_runtime.h>
#include <cuda_bf16.h>
#include <math.h>
#include <stdint.h>

// Problem constants
#define BATCH 32
#define NV    512
#define NQ    256
#define DMODEL 1024
#define D3    3072
#define NHEAD 8
#define DH    128

typedef __nv_bfloat16 bf16;

// ---------------------------------------------------------------------------
// Scratch (static device globals — allocation-free per harness rules)
// ---------------------------------------------------------------------------
__device__ float g_vmean[BATCH * DMODEL];
__device__ float g_qmean[BATCH * DMODEL];
__device__ float g_gate_v[BATCH * DMODEL];
__device__ float g_gate_q[BATCH * DMODEL];
__device__ float g_vtran[BATCH * NV * D3];
__device__ float g_qtran[BATCH * NQ * D3];
__device__ float g_vupd[BATCH * NV * DMODEL];
__device__ float g_qupd[BATCH * NQ * DMODEL];
// bf16 split operand buffers
__device__ bf16 g_Av_hi[BATCH * NV * DMODEL];
__device__ bf16 g_Av_lo[BATCH * NV * DMODEL];
__device__ bf16 g_Aq_hi[BATCH * NQ * DMODEL];
__device__ bf16 g_Aq_lo[BATCH * NQ * DMODEL];
__device__ bf16 g_Wvl_hi[DMODEL * D3];
__device__ bf16 g_Wvl_lo[DMODEL * D3];
__device__ bf16 g_Wql_hi[DMODEL * D3];
__device__ bf16 g_Wql_lo[DMODEL * D3];
__device__ bf16 g_Wvo_hi[DMODEL * DMODEL];
__device__ bf16 g_Wvo_lo[DMODEL * DMODEL];
__device__ bf16 g_Wqo_hi[DMODEL * DMODEL];
__device__ bf16 g_Wqo_lo[DMODEL * DMODEL];

// ---------------------------------------------------------------------------
// PTX helpers (Ampere-class: cp.async / ldmatrix / mma.sync)
// ---------------------------------------------------------------------------
__device__ __forceinline__ uint32_t smem_u32(const void* p) {
    uint32_t a;
    asm("{ .reg .u64 t; cvta.to.shared.u64 t, %1; cvt.u32.u64 %0, t; }" : "=r"(a) : "l"(p));
    return a;
}
__device__ __forceinline__ void cp_async16(uint32_t dst, const void* src) {
    asm volatile("cp.async.cg.shared.global [%0], [%1], 16;" :: "r"(dst), "l"(src));
}
#define CP_COMMIT() asm volatile("cp.async.commit_group;" ::: "memory")
#define CP_WAIT(n)  asm volatile("cp.async.wait_group %0;" :: "n"(n) : "memory")

__device__ __forceinline__ void ldsm_x4(uint32_t* d, uint32_t addr) {
    asm volatile("ldmatrix.sync.aligned.m8n8.x4.shared.b16 {%0,%1,%2,%3}, [%4];"
                 : "=r"(d[0]), "=r"(d[1]), "=r"(d[2]), "=r"(d[3]) : "r"(addr));
}
__device__ __forceinline__ void ldsm_x4_t(uint32_t* d, uint32_t addr) {
    asm volatile("ldmatrix.sync.aligned.m8n8.x4.trans.shared.b16 {%0,%1,%2,%3}, [%4];"
                 : "=r"(d[0]), "=r"(d[1]), "=r"(d[2]), "=r"(d[3]) : "r"(addr));
}
__device__ __forceinline__ void mma_bf16(float* c, const uint32_t* a, const uint32_t* b) {
    asm volatile(
        "mma.sync.aligned.m16n8k16.row.col.f32.bf16.bf16.f32 "
        "{%0,%1,%2,%3}, {%4,%5,%6,%7}, {%8,%9}, {%0,%1,%2,%3};"
        : "+f"(c[0]), "+f"(c[1]), "+f"(c[2]), "+f"(c[3])
        : "r"(a[0]), "r"(a[1]), "r"(a[2]), "r"(a[3]), "r"(b[0]), "r"(b[1]));
}

// ---------------------------------------------------------------------------
// Elementwise split kernels (fp32 -> bf16 hi + bf16 lo)
// ---------------------------------------------------------------------------
__global__ void split2_kernel(const float* __restrict__ x, bf16* __restrict__ hi,
                              bf16* __restrict__ lo, int n) {
    int i = (blockIdx.x * 256 + threadIdx.x) * 4;
    if (i >= n) return;
    float4 v = *(const float4*)(x + i);
    bf16 h0 = __float2bfloat16(v.x), h1 = __float2bfloat16(v.y);
    bf16 h2 = __float2bfloat16(v.z), h3 = __float2bfloat16(v.w);
    bf16 l0 = __float2bfloat16(v.x - __bfloat162float(h0));
    bf16 l1 = __float2bfloat16(v.y - __bfloat162float(h1));
    bf16 l2 = __float2bfloat16(v.z - __bfloat162float(h2));
    bf16 l3 = __float2bfloat16(v.w - __bfloat162float(h3));
    *(__nv_bfloat162*)(hi + i)     = __nv_bfloat162(h0, h1);
    *(__nv_bfloat162*)(hi + i + 2) = __nv_bfloat162(h2, h3);
    *(__nv_bfloat162*)(lo + i)     = __nv_bfloat162(l0, l1);
    *(__nv_bfloat162*)(lo + i + 2) = __nv_bfloat162(l2, l3);
}

__global__ void addsplit2_kernel(const float* __restrict__ x, const float* __restrict__ y,
                                 bf16* __restrict__ hi, bf16* __restrict__ lo, int n) {
    int i = (blockIdx.x * 256 + threadIdx.x) * 4;
    if (i >= n) return;
    float4 a = *(const float4*)(x + i);
    float4 b = *(const float4*)(y + i);
    a.x += b.x; a.y += b.y; a.z += b.z; a.w += b.w;
    bf16 h0 = __float2bfloat16(a.x), h1 = __float2bfloat16(a.y);
    bf16 h2 = __float2bfloat16(a.z), h3 = __float2bfloat16(a.w);
    bf16 l0 = __float2bfloat16(a.x - __bfloat162float(h0));
    bf16 l1 = __float2bfloat16(a.y - __bfloat162float(h1));
    bf16 l2 = __float2bfloat16(a.z - __bfloat162float(h2));
    bf16 l3 = __float2bfloat16(a.w - __bfloat162float(h3));
    *(__nv_bfloat162*)(hi + i)     = __nv_bfloat162(h0, h1);
    *(__nv_bfloat162*)(hi + i + 2) = __nv_bfloat162(h2, h3);
    *(__nv_bfloat162*)(lo + i)     = __nv_bfloat162(l0, l1);
    *(__nv_bfloat162*)(lo + i + 2) = __nv_bfloat162(l2, l3);
}

// ---------------------------------------------------------------------------
// Row means
// ---------------------------------------------------------------------------
__global__ void mean_kernel(const float* __restrict__ x, float* __restrict__ out, int nrows) {
    int b = blockIdx.x;
    int d = blockIdx.y * 256 + threadIdx.x;
    const float* p = x + (size_t)b * nrows * DMODEL + d;
    float s0 = 0.f, s1 = 0.f, s2 = 0.f, s3 = 0.f;
    for (int n = 0; n < nrows; n += 4) {
        s0 += p[(size_t)(n + 0) * DMODEL];
        s1 += p[(size_t)(n + 1) * DMODEL];
        s2 += p[(size_t)(n + 2) * DMODEL];
        s3 += p[(size_t)(n + 3) * DMODEL];
    }
    out[b * DMODEL + d] = (s0 + s1 + s2 + s3) / (float)nrows;
}

// ---------------------------------------------------------------------------
// Gates
// ---------------------------------------------------------------------------
__global__ __launch_bounds__(128)
void gate_kernel(const float* __restrict__ mean, const float* __restrict__ W,
                 const float* __restrict__ bias, float* __restrict__ gate) {
    __shared__ float sm[DMODEL];
    int b = blockIdx.x;
    int d = blockIdx.y * 128 + threadIdx.x;
    for (int i = threadIdx.x; i < DMODEL; i += 128) sm[i] = mean[b * DMODEL + i];
    __syncthreads();
    float a0 = 0.f, a1 = 0.f, a2 = 0.f, a3 = 0.f;
#pragma unroll 4
    for (int k = 0; k < DMODEL; k += 4) {
        a0 += sm[k + 0] * __ldg(&W[(size_t)(k + 0) * DMODEL + d]);
        a1 += sm[k + 1] * __ldg(&W[(size_t)(k + 1) * DMODEL + d]);
        a2 += sm[k + 2] * __ldg(&W[(size_t)(k + 2) * DMODEL + d]);
        a3 += sm[k + 3] * __ldg(&W[(size_t)(k + 3) * DMODEL + d]);
    }
    float acc = (a0 + a1) + (a2 + a3) + bias[d];
    gate[b * DMODEL + d] = 1.0f + 1.0f / (1.0f + __expf(-acc));
}

// ---------------------------------------------------------------------------
// Split-bf16 mma.sync GEMM.  C[M,N] = epi( A @ B + bias )
// A=[M,K] hi/lo bf16 row-major, B=[K,N] hi/lo bf16 row-major.
// CTA 128x128, BK=32, 256 threads (8 warps: 4x2), warp tile 32x64.
// 3-stage cp.async pipeline. ldmatrix fragment loads.
// ---------------------------------------------------------------------------
// smem stage layout (bytes):
//   Ah: 128 rows * 80  = 10240      (row stride 40 bf16 = 80 B)
//   Al: +10240
//   Bh: 32 rows * 272  =  8704      (row stride 136 bf16 = 272 B)  at +20480
//   Bl: +29184
//   stage stride 37888; 3 stages = 113664 B
#define GSTAGE 37888
#define GOFF_AL 10240
#define GOFF_BH 20480
#define GOFF_BL 29184

template <bool GATE>
__global__ __launch_bounds__(256)
void bmma_gemm(const bf16* __restrict__ Ahi, const bf16* __restrict__ Alo,
               const bf16* __restrict__ Bhi, const bf16* __restrict__ Blo,
               const float* __restrict__ bias, const float* __restrict__ gate,
               float* __restrict__ C, int M, int N, int K, int rows_per_batch) {
    extern __shared__ __align__(16) char smem[];
    const uint32_t sb = smem_u32(smem);
    const int tid = threadIdx.x;
    const int warp = tid >> 5, lane = tid & 31;
    const int wm = warp & 3, wn = warp >> 2;
    const int m0 = blockIdx.y * 128, n0 = blockIdx.x * 128;
    const int NST = K >> 5;   // K/32

    auto load_stage = [&](int s) {
        const uint32_t buf = sb + (uint32_t)(s % 3) * GSTAGE;
        const int k0 = s * 32;
#pragma unroll
        for (int i = 0; i < 2; i++) {
            int c = tid + i * 256;
            // A: 128 rows x 4 chunks of 16B (8 bf16)
            {
                int row = c >> 2, kc = c & 3;
                size_t g = (size_t)(m0 + row) * K + k0 + kc * 8;
                uint32_t d = buf + (uint32_t)(row * 80 + kc * 16);
                cp_async16(d, Ahi + g);
                cp_async16(d + GOFF_AL, Alo + g);
            }
            // B: 32 k-rows x 16 chunks of 16B
            {
                int row = c >> 4, nc = c & 15;
                size_t g = (size_t)(k0 + row) * N + n0 + nc * 8;
                uint32_t d = buf + GOFF_BH + (uint32_t)(row * 272 + nc * 16);
                cp_async16(d, Bhi + g);
                cp_async16(d + (GOFF_BL - GOFF_BH), Blo + g);
            }
        }
    };

    float acc[2][8][4];
#pragma unroll
    for (int i = 0; i < 2; i++)
#pragma unroll
        for (int j = 0; j < 8; j++)
#pragma unroll
            for (int t = 0; t < 4; t++) acc[i][j][t] = 0.f;

    load_stage(0); CP_COMMIT();
    load_stage(1); CP_COMMIT();

    // ldmatrix lane addressing (constant per thread)
    const int lr = lane & 15;          // row within 16
    const int lc = lane >> 4;          // 0/1 -> +8 cols
    for (int s = 0; s < NST; s++) {
        if (s + 1 < NST) { CP_WAIT(1); } else { CP_WAIT(0); }
        __syncthreads();
        const uint32_t buf = sb + (uint32_t)(s % 3) * GSTAGE;
#pragma unroll
        for (int ks = 0; ks < 2; ks++) {
            uint32_t ah[2][4], al[2][4];
#pragma unroll
            for (int mi = 0; mi < 2; mi++) {
                uint32_t addr = buf + (uint32_t)((wm * 32 + mi * 16 + lr) * 80 + ks * 32 + lc * 16);
                ldsm_x4(ah[mi], addr);
                ldsm_x4(al[mi], addr + GOFF_AL);
            }
            uint32_t bh[8][2], bl[8][2];
#pragma unroll
            for (int nio = 0; nio < 4; nio++) {
                uint32_t addr = buf + GOFF_BH +
                    (uint32_t)((ks * 16 + lr) * 272 + wn * 128 + nio * 32 + lc * 16);
                uint32_t t4[4];
                ldsm_x4_t(t4, addr);
                bh[nio * 2][0] = t4[0]; bh[nio * 2][1] = t4[1];
                bh[nio * 2 + 1][0] = t4[2]; bh[nio * 2 + 1][1] = t4[3];
                ldsm_x4_t(t4, addr + (GOFF_BL - GOFF_BH));
                bl[nio * 2][0] = t4[0]; bl[nio * 2][1] = t4[1];
                bl[nio * 2 + 1][0] = t4[2]; bl[nio * 2 + 1][1] = t4[3];
            }
#pragma unroll
            for (int mi = 0; mi < 2; mi++)
#pragma unroll
                for (int ni = 0; ni < 8; ni++) {
                    mma_bf16(acc[mi][ni], ah[mi], bh[ni]);
                    mma_bf16(acc[mi][ni], al[mi], bh[ni]);
                    mma_bf16(acc[mi][ni], ah[mi], bl[ni]);
                }
        }
        if (s + 2 < NST) { load_stage(s + 2); CP_COMMIT(); }
    }

    // epilogue
    const int gid = lane >> 2, tig = lane & 3;
    const int b_idx = GATE ? (m0 / rows_per_batch) : 0;
#pragma unroll
    for (int mi = 0; mi < 2; mi++) {
        int r = m0 + wm * 32 + mi * 16 + gid;
#pragma unroll
        for (int ni = 0; ni < 8; ni++) {
            int c = n0 + wn * 64 + ni * 8 + tig * 2;
            float g0 = 1.f, g1 = 1.f;
            if (GATE) {
                g0 = gate[b_idx * DMODEL + (c & (DMODEL - 1))];
                g1 = gate[b_idx * DMODEL + ((c + 1) & (DMODEL - 1))];
            }
            float bz0 = bias[c], bz1 = bias[c + 1];
            float2 o0, o1;
            o0.x = fmaxf(acc[mi][ni][0] + bz0, 0.f) * g0;
            o0.y = fmaxf(acc[mi][ni][1] + bz1, 0.f) * g1;
            o1.x = fmaxf(acc[mi][ni][2] + bz0, 0.f) * g0;
            o1.y = fmaxf(acc[mi][ni][3] + bz1, 0.f) * g1;
            *(float2*)&C[(size_t)r * N + c] = o0;
            *(float2*)&C[(size_t)(r + 8) * N + c] = o1;
        }
    }
}

// ---------------------------------------------------------------------------
// Multi-head self-attention (fp32, unchanged from round 2 — known good)
// ---------------------------------------------------------------------------
template <int NK, int NROWS>
__global__ __launch_bounds__(128)
void attn_kernel(const float* __restrict__ tran, float* __restrict__ upd) {
    constexpr int TQ = 16, TK = 64;
    constexpr int QS = DH + 4;
    constexpr int SS = NK + 4;
    extern __shared__ float smf[];
    float* Qs   = smf;
    float* KV   = Qs + TQ * QS;
    float* S    = KV + TK * QS;
    float* rinv = S + TQ * SS;

    const int tid = threadIdx.x;
    const int qt = blockIdx.x, h = blockIdx.y, b = blockIdx.z;
    const size_t base = (size_t)b * NROWS * D3 + (size_t)h * DH;
    const int q0 = qt * TQ;

    for (int idx = tid; idx < TQ * DH; idx += 128) {
        int qi = idx / DH, d = idx % DH;
        Qs[qi * QS + d] = tran[base + (size_t)(q0 + qi) * D3 + DMODEL + d];
    }

    const int sq = tid >> 3;
    const int sk = tid & 7;

    for (int kt = 0; kt < NK; kt += TK) {
        __syncthreads();
        for (int idx = tid; idx < TK * DH; idx += 128) {
            int r = idx / DH, d = idx % DH;
            KV[r * QS + d] = tran[base + (size_t)(kt + r) * D3 + d];
        }
        __syncthreads();
        float acc[8];
#pragma unroll
        for (int j = 0; j < 8; j++) acc[j] = 0.f;
        for (int d = 0; d < DH; d += 4) {
            float4 qv = *(float4*)&Qs[sq * QS + d];
#pragma unroll
            for (int j = 0; j < 8; j++) {
                float4 kv = *(float4*)&KV[(sk + 8 * j) * QS + d];
                acc[j] += qv.x * kv.x + qv.y * kv.y + qv.z * kv.z + qv.w * kv.w;
            }
        }
        const float scale = 0.08838834764831845f;
#pragma unroll
        for (int j = 0; j < 8; j++) S[sq * SS + kt + sk + 8 * j] = acc[j] * scale;
    }
    __syncthreads();

    {
        float m = -1e30f;
        for (int c = sk; c < NK; c += 8) m = fmaxf(m, S[sq * SS + c]);
        m = fmaxf(m, __shfl_xor_sync(0xffffffffu, m, 1));
        m = fmaxf(m, __shfl_xor_sync(0xffffffffu, m, 2));
        m = fmaxf(m, __shfl_xor_sync(0xffffffffu, m, 4));
        float s = 0.f;
        for (int c = sk; c < NK; c += 8) {
            float e = __expf(S[sq * SS + c] - m);
            S[sq * SS + c] = e;
            s += e;
        }
        s += __shfl_xor_sync(0xffffffffu, s, 1);
        s += __shfl_xor_sync(0xffffffffu, s, 2);
        s += __shfl_xor_sync(0xffffffffu, s, 4);
        if (sk == 0) rinv[sq] = 1.0f / s;
    }

    const int dsub = sk * 16;
    float o[16];
#pragma unroll
    for (int j = 0; j < 16; j++) o[j] = 0.f;
    for (int kt = 0; kt < NK; kt += TK) {
        __syncthreads();
        for (int idx = tid; idx < TK * DH; idx += 128) {
            int r = idx / DH, d = idx % DH;
            KV[r * QS + d] = tran[base + (size_t)(kt + r) * D3 + 2 * DMODEL + d];
        }
        __syncthreads();
        for (int k = 0; k < TK; k++) {
            float p = S[sq * SS + kt + k];
#pragma unroll
            for (int j4 = 0; j4 < 16; j4 += 4) {
                float4 vv = *(float4*)&KV[k * QS + dsub + j4];
                o[j4 + 0] += p * vv.x;
                o[j4 + 1] += p * vv.y;
                o[j4 + 2] += p * vv.z;
                o[j4 + 3] += p * vv.w;
            }
        }
    }
    const float inv = rinv[sq];
    float* dst = upd + (size_t)(b * NROWS + q0 + sq) * DMODEL + h * DH + dsub;
#pragma unroll
    for (int j4 = 0; j4 < 16; j4 += 4) {
        float4 ov = {o[j4] * inv, o[j4 + 1] * inv, o[j4 + 2] * inv, o[j4 + 3] * inv};
        *(float4*)&dst[j4] = ov;
    }
}

// ---------------------------------------------------------------------------
// launch
// ---------------------------------------------------------------------------
extern "C" void kernel_launch(void* const* d_in, const int* in_sizes, int n_in,
                              void* d_out, int out_size) {
    const float* v      = (const float*)d_in[0];
    const float* q      = (const float*)d_in[1];
    const float* w_v4q  = (const float*)d_in[2];
    const float* b_v4q  = (const float*)d_in[3];
    const float* w_q4v  = (const float*)d_in[4];
    const float* b_q4v  = (const float*)d_in[5];
    const float* w_vlin = (const float*)d_in[6];
    const float* b_vlin = (const float*)d_in[7];
    const float* w_qlin = (const float*)d_in[8];
    const float* b_qlin = (const float*)d_in[9];
    const float* w_vout = (const float*)d_in[10];
    const float* b_vout = (const float*)d_in[11];
    const float* w_qout = (const float*)d_in[12];
    const float* b_qout = (const float*)d_in[13];

    float* out_v = (float*)d_out;
    float* out_q = out_v + (size_t)BATCH * NV * DMODEL;

    float *p_vmean, *p_qmean, *p_gv, *p_gq, *p_vtran, *p_qtran, *p_vupd, *p_qupd;
    cudaGetSymbolAddress((void**)&p_vmean, g_vmean);
    cudaGetSymbolAddress((void**)&p_qmean, g_qmean);
    cudaGetSymbolAddress((void**)&p_gv,    g_gate_v);
    cudaGetSymbolAddress((void**)&p_gq,    g_gate_q);
    cudaGetSymbolAddress((void**)&p_vtran, g_vtran);
    cudaGetSymbolAddress((void**)&p_qtran, g_qtran);
    cudaGetSymbolAddress((void**)&p_vupd,  g_vupd);
    cudaGetSymbolAddress((void**)&p_qupd,  g_qupd);

    bf16 *Av_hi, *Av_lo, *Aq_hi, *Aq_lo;
    bf16 *Wvl_hi, *Wvl_lo, *Wql_hi, *Wql_lo, *Wvo_hi, *Wvo_lo, *Wqo_hi, *Wqo_lo;
    cudaGetSymbolAddress((void**)&Av_hi, g_Av_hi);
    cudaGetSymbolAddress((void**)&Av_lo, g_Av_lo);
    cudaGetSymbolAddress((void**)&Aq_hi, g_Aq_hi);
    cudaGetSymbolAddress((void**)&Aq_lo, g_Aq_lo);
    cudaGetSymbolAddress((void**)&Wvl_hi, g_Wvl_hi);
    cudaGetSymbolAddress((void**)&Wvl_lo, g_Wvl_lo);
    cudaGetSymbolAddress((void**)&Wql_hi, g_Wql_hi);
    cudaGetSymbolAddress((void**)&Wql_lo, g_Wql_lo);
    cudaGetSymbolAddress((void**)&Wvo_hi, g_Wvo_hi);
    cudaGetSymbolAddress((void**)&Wvo_lo, g_Wvo_lo);
    cudaGetSymbolAddress((void**)&Wqo_hi, g_Wqo_hi);
    cudaGetSymbolAddress((void**)&Wqo_lo, g_Wqo_lo);

    const int SMEM_G = 3 * GSTAGE;   // 113664
    cudaFuncSetAttribute(bmma_gemm<true>,  cudaFuncAttributeMaxDynamicSharedMemorySize, SMEM_G);
    cudaFuncSetAttribute(bmma_gemm<false>, cudaFuncAttributeMaxDynamicSharedMemorySize, SMEM_G);

    const int smemV = (16 * 132 + 64 * 132 + 16 * (512 + 4) + 16) * (int)sizeof(float);
    const int smemQ = (16 * 132 + 64 * 132 + 16 * (256 + 4) + 16) * (int)sizeof(float);
    cudaFuncSetAttribute(attn_kernel<512, NV>, cudaFuncAttributeMaxDynamicSharedMemorySize, smemV);
    cudaFuncSetAttribute(attn_kernel<256, NQ>, cudaFuncAttributeMaxDynamicSharedMemorySize, smemQ);

    // means + gates
    mean_kernel<<<dim3(BATCH, 4), 256>>>(v, p_vmean, NV);
    mean_kernel<<<dim3(BATCH, 4), 256>>>(q, p_qmean, NQ);
    gate_kernel<<<dim3(BATCH, 8), 128>>>(p_vmean, w_v4q, b_v4q, p_gq);
    gate_kernel<<<dim3(BATCH, 8), 128>>>(p_qmean, w_q4v, b_q4v, p_gv);

    // operand splits
    const int nAv = BATCH * NV * DMODEL, nAq = BATCH * NQ * DMODEL;
    const int nWl = DMODEL * D3, nWo = DMODEL * DMODEL;
    split2_kernel<<<nAv / 1024, 256>>>(v, Av_hi, Av_lo, nAv);
    split2_kernel<<<nAq / 1024, 256>>>(q, Aq_hi, Aq_lo, nAq);
    split2_kernel<<<nWl / 1024, 256>>>(w_vlin, Wvl_hi, Wvl_lo, nWl);
    split2_kernel<<<nWl / 1024, 256>>>(w_qlin, Wql_hi, Wql_lo, nWl);
    split2_kernel<<<nWo / 1024, 256>>>(w_vout, Wvo_hi, Wvo_lo, nWo);
    split2_kernel<<<nWo / 1024, 256>>>(w_qout, Wqo_hi, Wqo_lo, nWo);

    // gated tran projections
    bmma_gemm<true><<<dim3(D3 / 128, BATCH * NV / 128), 256, SMEM_G>>>(
        Av_hi, Av_lo, Wvl_hi, Wvl_lo, b_vlin, p_gv, p_vtran, BATCH * NV, D3, DMODEL, NV);
    bmma_gemm<true><<<dim3(D3 / 128, BATCH * NQ / 128), 256, SMEM_G>>>(
        Aq_hi, Aq_lo, Wql_hi, Wql_lo, b_qlin, p_gq, p_qtran, BATCH * NQ, D3, DMODEL, NQ);

    // attention
    attn_kernel<512, NV><<<dim3(NV / 16, NHEAD, BATCH), 128, smemV>>>(p_vtran, p_vupd);
    attn_kernel<256, NQ><<<dim3(NQ / 16, NHEAD, BATCH), 128, smemQ>>>(p_qtran, p_qupd);

    // residual add + split (reuse A buffers)
    addsplit2_kernel<<<nAv / 1024, 256>>>(v, p_vupd, Av_hi, Av_lo, nAv);
    addsplit2_kernel<<<nAq / 1024, 256>>>(q, p_qupd, Aq_hi, Aq_lo, nAq);

    // output projections
    bmma_gemm<false><<<dim3(DMODEL / 128, BATCH * NV / 128), 256, SMEM_G>>>(
        Av_hi, Av_lo, Wvo_hi, Wvo_lo, b_vout, nullptr, out_v, BATCH * NV, DMODEL, DMODEL, NV);
    bmma_gemm<false><<<dim3(DMODEL / 128, BATCH * NQ / 128), 256, SMEM_G>>>(
        Aq_hi, Aq_lo, Wqo_hi, Wqo_lo, b_qout, nullptr, out_q, BATCH * NQ, DMODEL, DMODEL, NQ);
}

// round 6
// speedup vs baseline: 2.3921x; 1.7331x over previous
#include <cuda_runtime.h>
#include <cuda_fp16.h>
#include <math.h>
#include <stdint.h>

// Problem constants
#define BATCH 32
#define NV    512
#define NQ    256
#define DMODEL 1024
#define D3    3072
#define NHEAD 8
#define DH    128

// ---------------------------------------------------------------------------
// Scratch (static device globals — allocation-free per harness rules)
// ---------------------------------------------------------------------------
__device__ float g_vmean[BATCH * DMODEL];
__device__ float g_qmean[BATCH * DMODEL];
__device__ float g_gate_v[BATCH * DMODEL];
__device__ float g_gate_q[BATCH * DMODEL];
__device__ float g_vtran[BATCH * NV * D3];
__device__ float g_qtran[BATCH * NQ * D3];
__device__ float g_vupd[BATCH * NV * DMODEL];
__device__ float g_qupd[BATCH * NQ * DMODEL];
// fp16 split operand buffers (A: hi+lo, W: hi only)
__device__ __half g_Av_hi[BATCH * NV * DMODEL];
__device__ __half g_Av_lo[BATCH * NV * DMODEL];
__device__ __half g_Aq_hi[BATCH * NQ * DMODEL];
__device__ __half g_Aq_lo[BATCH * NQ * DMODEL];
__device__ __half g_Wvl_hi[DMODEL * D3];
__device__ __half g_Wql_hi[DMODEL * D3];
__device__ __half g_Wvo_hi[DMODEL * DMODEL];
__device__ __half g_Wqo_hi[DMODEL * DMODEL];

// ---------------------------------------------------------------------------
// PTX helpers (cp.async / ldmatrix / mma.sync)
// ---------------------------------------------------------------------------
__device__ __forceinline__ uint32_t smem_u32(const void* p) {
    uint32_t a;
    asm("{ .reg .u64 t; cvta.to.shared.u64 t, %1; cvt.u32.u64 %0, t; }" : "=r"(a) : "l"(p));
    return a;
}
__device__ __forceinline__ void cp_async16(uint32_t dst, const void* src) {
    asm volatile("cp.async.cg.shared.global [%0], [%1], 16;" :: "r"(dst), "l"(src));
}
#define CP_COMMIT() asm volatile("cp.async.commit_group;" ::: "memory")
#define CP_WAIT(n)  asm volatile("cp.async.wait_group %0;" :: "n"(n) : "memory")

__device__ __forceinline__ void ldsm_x4(uint32_t* d, uint32_t addr) {
    asm volatile("ldmatrix.sync.aligned.m8n8.x4.shared.b16 {%0,%1,%2,%3}, [%4];"
                 : "=r"(d[0]), "=r"(d[1]), "=r"(d[2]), "=r"(d[3]) : "r"(addr));
}
__device__ __forceinline__ void ldsm_x4_t(uint32_t* d, uint32_t addr) {
    asm volatile("ldmatrix.sync.aligned.m8n8.x4.trans.shared.b16 {%0,%1,%2,%3}, [%4];"
                 : "=r"(d[0]), "=r"(d[1]), "=r"(d[2]), "=r"(d[3]) : "r"(addr));
}
__device__ __forceinline__ void mma_f16(float* c, const uint32_t* a, const uint32_t* b) {
    asm volatile(
        "mma.sync.aligned.m16n8k16.row.col.f32.f16.f16.f32 "
        "{%0,%1,%2,%3}, {%4,%5,%6,%7}, {%8,%9}, {%0,%1,%2,%3};"
        : "+f"(c[0]), "+f"(c[1]), "+f"(c[2]), "+f"(c[3])
        : "r"(a[0]), "r"(a[1]), "r"(a[2]), "r"(a[3]), "r"(b[0]), "r"(b[1]));
}

// ---------------------------------------------------------------------------
// Elementwise conversion kernels
// ---------------------------------------------------------------------------
__global__ void split2_kernel(const float* __restrict__ x, __half* __restrict__ hi,
                              __half* __restrict__ lo, int n) {
    int i = (blockIdx.x * 256 + threadIdx.x) * 4;
    if (i >= n) return;
    float4 v = *(const float4*)(x + i);
    __half h0 = __float2half_rn(v.x), h1 = __float2half_rn(v.y);
    __half h2 = __float2half_rn(v.z), h3 = __float2half_rn(v.w);
    __half l0 = __float2half_rn(v.x - __half2float(h0));
    __half l1 = __float2half_rn(v.y - __half2float(h1));
    __half l2 = __float2half_rn(v.z - __half2float(h2));
    __half l3 = __float2half_rn(v.w - __half2float(h3));
    *(__half2*)(hi + i)     = __half2(h0, h1);
    *(__half2*)(hi + i + 2) = __half2(h2, h3);
    *(__half2*)(lo + i)     = __half2(l0, l1);
    *(__half2*)(lo + i + 2) = __half2(l2, l3);
}

__global__ void addsplit2_kernel(const float* __restrict__ x, const float* __restrict__ y,
                                 __half* __restrict__ hi, __half* __restrict__ lo, int n) {
    int i = (blockIdx.x * 256 + threadIdx.x) * 4;
    if (i >= n) return;
    float4 a = *(const float4*)(x + i);
    float4 b = *(const float4*)(y + i);
    a.x += b.x; a.y += b.y; a.z += b.z; a.w += b.w;
    __half h0 = __float2half_rn(a.x), h1 = __float2half_rn(a.y);
    __half h2 = __float2half_rn(a.z), h3 = __float2half_rn(a.w);
    __half l0 = __float2half_rn(a.x - __half2float(h0));
    __half l1 = __float2half_rn(a.y - __half2float(h1));
    __half l2 = __float2half_rn(a.z - __half2float(h2));
    __half l3 = __float2half_rn(a.w - __half2float(h3));
    *(__half2*)(hi + i)     = __half2(h0, h1);
    *(__half2*)(hi + i + 2) = __half2(h2, h3);
    *(__half2*)(lo + i)     = __half2(l0, l1);
    *(__half2*)(lo + i + 2) = __half2(l2, l3);
}

__global__ void tohalf_kernel(const float* __restrict__ x, __half* __restrict__ hi, int n) {
    int i = (blockIdx.x * 256 + threadIdx.x) * 4;
    if (i >= n) return;
    float4 v = *(const float4*)(x + i);
    *(__half2*)(hi + i)     = __half2(__float2half_rn(v.x), __float2half_rn(v.y));
    *(__half2*)(hi + i + 2) = __half2(__float2half_rn(v.z), __float2half_rn(v.w));
}

// ---------------------------------------------------------------------------
// Row means
// ---------------------------------------------------------------------------
__global__ void mean_kernel(const float* __restrict__ x, float* __restrict__ out, int nrows) {
    int b = blockIdx.x;
    int d = blockIdx.y * 256 + threadIdx.x;
    const float* p = x + (size_t)b * nrows * DMODEL + d;
    float s0 = 0.f, s1 = 0.f, s2 = 0.f, s3 = 0.f;
    for (int n = 0; n < nrows; n += 4) {
        s0 += p[(size_t)(n + 0) * DMODEL];
        s1 += p[(size_t)(n + 1) * DMODEL];
        s2 += p[(size_t)(n + 2) * DMODEL];
        s3 += p[(size_t)(n + 3) * DMODEL];
    }
    out[b * DMODEL + d] = (s0 + s1 + s2 + s3) / (float)nrows;
}

// ---------------------------------------------------------------------------
// Gates: k-split 4 ways across 512 threads, smem reduce
// ---------------------------------------------------------------------------
__global__ __launch_bounds__(512)
void gate_kernel(const float* __restrict__ mean, const float* __restrict__ W,
                 const float* __restrict__ bias, float* __restrict__ gate) {
    __shared__ float sm[DMODEL];
    __shared__ float part[4][128];
    const int b = blockIdx.x;
    const int l = threadIdx.x & 127;
    const int ks = threadIdx.x >> 7;
    const int d = blockIdx.y * 128 + l;
    for (int i = threadIdx.x; i < DMODEL; i += 512) sm[i] = mean[b * DMODEL + i];
    __syncthreads();
    const int k0 = ks * 256;
    float a0 = 0.f, a1 = 0.f, a2 = 0.f, a3 = 0.f;
#pragma unroll 4
    for (int k = 0; k < 256; k += 4) {
        a0 += sm[k0 + k + 0] * __ldg(&W[(size_t)(k0 + k + 0) * DMODEL + d]);
        a1 += sm[k0 + k + 1] * __ldg(&W[(size_t)(k0 + k + 1) * DMODEL + d]);
        a2 += sm[k0 + k + 2] * __ldg(&W[(size_t)(k0 + k + 2) * DMODEL + d]);
        a3 += sm[k0 + k + 3] * __ldg(&W[(size_t)(k0 + k + 3) * DMODEL + d]);
    }
    part[ks][l] = (a0 + a1) + (a2 + a3);
    __syncthreads();
    if (ks == 0) {
        float acc = part[0][l] + part[1][l] + part[2][l] + part[3][l] + bias[d];
        gate[b * DMODEL + d] = 1.0f + 1.0f / (1.0f + __expf(-acc));
    }
}

// ---------------------------------------------------------------------------
// Split-fp16 2-pass mma GEMM.  C[M,N] = epi( (Ah+Al) @ Wh + bias )
// CTA 128x128, BK=32, 256 threads (8 warps: 4x2), warp tile 32x64.
// 3-stage cp.async pipeline, ldmatrix fragment loads.
// smem stage: Ah 128*80=10240 | Al +10240 | Bh 32*272=8704 at +20480
// stage stride 29184; 3 stages = 87552 B  -> 2 CTAs/SM
// ---------------------------------------------------------------------------
#define GSTAGE 29184
#define GOFF_AL 10240
#define GOFF_BH 20480

template <bool GATE>
__global__ __launch_bounds__(256)
void bmma_gemm(const __half* __restrict__ Ahi, const __half* __restrict__ Alo,
               const __half* __restrict__ Bhi,
               const float* __restrict__ bias, const float* __restrict__ gate,
               float* __restrict__ C, int M, int N, int K, int rows_per_batch) {
    extern __shared__ __align__(16) char smem[];
    const uint32_t sb = smem_u32(smem);
    const int tid = threadIdx.x;
    const int warp = tid >> 5, lane = tid & 31;
    const int wm = warp & 3, wn = warp >> 2;
    const int m0 = blockIdx.y * 128, n0 = blockIdx.x * 128;
    const int NST = K >> 5;   // K/32

    auto load_stage = [&](int s) {
        const uint32_t buf = sb + (uint32_t)(s % 3) * GSTAGE;
        const int k0 = s * 32;
#pragma unroll
        for (int i = 0; i < 2; i++) {
            int c = tid + i * 256;
            // A: 128 rows x 4 chunks of 16B (8 halves)
            {
                int row = c >> 2, kc = c & 3;
                size_t g = (size_t)(m0 + row) * K + k0 + kc * 8;
                uint32_t d = buf + (uint32_t)(row * 80 + kc * 16);
                cp_async16(d, Ahi + g);
                cp_async16(d + GOFF_AL, Alo + g);
            }
            // B: 32 k-rows x 16 chunks of 16B
            {
                int row = c >> 4, nc = c & 15;
                size_t g = (size_t)(k0 + row) * N + n0 + nc * 8;
                cp_async16(buf + GOFF_BH + (uint32_t)(row * 272 + nc * 16), Bhi + g);
            }
        }
    };

    float acc[2][8][4];
#pragma unroll
    for (int i = 0; i < 2; i++)
#pragma unroll
        for (int j = 0; j < 8; j++)
#pragma unroll
            for (int t = 0; t < 4; t++) acc[i][j][t] = 0.f;

    load_stage(0); CP_COMMIT();
    load_stage(1); CP_COMMIT();

    const int lr = lane & 15;
    const int lc = lane >> 4;
    for (int s = 0; s < NST; s++) {
        if (s + 1 < NST) { CP_WAIT(1); } else { CP_WAIT(0); }
        __syncthreads();
        const uint32_t buf = sb + (uint32_t)(s % 3) * GSTAGE;
#pragma unroll
        for (int ks = 0; ks < 2; ks++) {
            uint32_t ah[2][4], al[2][4];
#pragma unroll
            for (int mi = 0; mi < 2; mi++) {
                uint32_t addr = buf + (uint32_t)((wm * 32 + mi * 16 + lr) * 80 + ks * 32 + lc * 16);
                ldsm_x4(ah[mi], addr);
                ldsm_x4(al[mi], addr + GOFF_AL);
            }
            uint32_t bh[8][2];
#pragma unroll
            for (int nio = 0; nio < 4; nio++) {
                uint32_t addr = buf + GOFF_BH +
                    (uint32_t)((ks * 16 + lr) * 272 + wn * 128 + nio * 32 + lc * 16);
                uint32_t t4[4];
                ldsm_x4_t(t4, addr);
                bh[nio * 2][0] = t4[0]; bh[nio * 2][1] = t4[1];
                bh[nio * 2 + 1][0] = t4[2]; bh[nio * 2 + 1][1] = t4[3];
            }
#pragma unroll
            for (int mi = 0; mi < 2; mi++)
#pragma unroll
                for (int ni = 0; ni < 8; ni++) {
                    mma_f16(acc[mi][ni], ah[mi], bh[ni]);
                    mma_f16(acc[mi][ni], al[mi], bh[ni]);
                }
        }
        if (s + 2 < NST) { load_stage(s + 2); CP_COMMIT(); }
    }

    // epilogue
    const int gid = lane >> 2, tig = lane & 3;
    const int b_idx = GATE ? (m0 / rows_per_batch) : 0;
#pragma unroll
    for (int mi = 0; mi < 2; mi++) {
        int r = m0 + wm * 32 + mi * 16 + gid;
#pragma unroll
        for (int ni = 0; ni < 8; ni++) {
            int c = n0 + wn * 64 + ni * 8 + tig * 2;
            float g0 = 1.f, g1 = 1.f;
            if (GATE) {
                g0 = gate[b_idx * DMODEL + (c & (DMODEL - 1))];
                g1 = gate[b_idx * DMODEL + ((c + 1) & (DMODEL - 1))];
            }
            float bz0 = bias[c], bz1 = bias[c + 1];
            float2 o0, o1;
            o0.x = fmaxf(acc[mi][ni][0] + bz0, 0.f) * g0;
            o0.y = fmaxf(acc[mi][ni][1] + bz1, 0.f) * g1;
            o1.x = fmaxf(acc[mi][ni][2] + bz0, 0.f) * g0;
            o1.y = fmaxf(acc[mi][ni][3] + bz1, 0.f) * g1;
            *(float2*)&C[(size_t)r * N + c] = o0;
            *(float2*)&C[(size_t)(r + 8) * N + c] = o1;
        }
    }
}

// ---------------------------------------------------------------------------
// Multi-head self-attention. Logits+softmax unchanged; PV restructured:
// warp w owns q rows {4w..4w+3}, lane owns 4 contiguous d-cols.
// ---------------------------------------------------------------------------
template <int NK, int NROWS>
__global__ __launch_bounds__(128)
void attn_kernel(const float* __restrict__ tran, float* __restrict__ upd) {
    constexpr int TQ = 16, TK = 64;
    constexpr int QS = DH + 4;
    constexpr int SS = NK + 4;
    extern __shared__ float smf[];
    float* Qs   = smf;
    float* KV   = Qs + TQ * QS;
    float* S    = KV + TK * QS;
    float* rinv = S + TQ * SS;

    const int tid = threadIdx.x;
    const int wid = tid >> 5, lane = tid & 31;
    const int qt = blockIdx.x, h = blockIdx.y, b = blockIdx.z;
    const size_t base = (size_t)b * NROWS * D3 + (size_t)h * DH;
    const int q0 = qt * TQ;

    for (int idx = tid; idx < TQ * DH; idx += 128) {
        int qi = idx / DH, d = idx % DH;
        Qs[qi * QS + d] = tran[base + (size_t)(q0 + qi) * D3 + DMODEL + d];
    }

    const int sq = tid >> 3;
    const int sk = tid & 7;

    // ---- logits ----
    for (int kt = 0; kt < NK; kt += TK) {
        __syncthreads();
        for (int idx = tid; idx < TK * DH; idx += 128) {
            int r = idx / DH, d = idx % DH;
            KV[r * QS + d] = tran[base + (size_t)(kt + r) * D3 + d];
        }
        __syncthreads();
        float acc[8];
#pragma unroll
        for (int j = 0; j < 8; j++) acc[j] = 0.f;
        for (int d = 0; d < DH; d += 4) {
            float4 qv = *(float4*)&Qs[sq * QS + d];
#pragma unroll
            for (int j = 0; j < 8; j++) {
                float4 kv = *(float4*)&KV[(sk + 8 * j) * QS + d];
                acc[j] += qv.x * kv.x + qv.y * kv.y + qv.z * kv.z + qv.w * kv.w;
            }
        }
        const float scale = 0.08838834764831845f;
#pragma unroll
        for (int j = 0; j < 8; j++) S[sq * SS + kt + sk + 8 * j] = acc[j] * scale;
    }
    __syncthreads();

    // ---- softmax ----
    {
        float m = -1e30f;
        for (int c = sk; c < NK; c += 8) m = fmaxf(m, S[sq * SS + c]);
        m = fmaxf(m, __shfl_xor_sync(0xffffffffu, m, 1));
        m = fmaxf(m, __shfl_xor_sync(0xffffffffu, m, 2));
        m = fmaxf(m, __shfl_xor_sync(0xffffffffu, m, 4));
        float s = 0.f;
        for (int c = sk; c < NK; c += 8) {
            float e = __expf(S[sq * SS + c] - m);
            S[sq * SS + c] = e;
            s += e;
        }
        s += __shfl_xor_sync(0xffffffffu, s, 1);
        s += __shfl_xor_sync(0xffffffffu, s, 2);
        s += __shfl_xor_sync(0xffffffffu, s, 4);
        if (sk == 0) rinv[sq] = 1.0f / s;
    }

    // ---- O = P @ V : warp w -> q rows 4w..4w+3, lane -> d cols lane*4..+3 ----
    float o[4][4];
#pragma unroll
    for (int qi = 0; qi < 4; qi++)
#pragma unroll
        for (int j = 0; j < 4; j++) o[qi][j] = 0.f;

    for (int kt = 0; kt < NK; kt += TK) {
        __syncthreads();
        for (int idx = tid; idx < TK * DH; idx += 128) {
            int r = idx / DH, d = idx % DH;
            KV[r * QS + d] = tran[base + (size_t)(kt + r) * D3 + 2 * DMODEL + d];
        }
        __syncthreads();
#pragma unroll 2
        for (int k = 0; k < TK; k++) {
            float4 vv = *(float4*)&KV[k * QS + lane * 4];
#pragma unroll
            for (int qi = 0; qi < 4; qi++) {
                float p = S[(wid * 4 + qi) * SS + kt + k];
                o[qi][0] += p * vv.x;
                o[qi][1] += p * vv.y;
                o[qi][2] += p * vv.z;
                o[qi][3] += p * vv.w;
            }
        }
    }
#pragma unroll
    for (int qi = 0; qi < 4; qi++) {
        const int qr = wid * 4 + qi;
        const float inv = rinv[qr];
        float4 ov = {o[qi][0] * inv, o[qi][1] * inv, o[qi][2] * inv, o[qi][3] * inv};
        *(float4*)&upd[(size_t)(b * NROWS + q0 + qr) * DMODEL + h * DH + lane * 4] = ov;
    }
}

// ---------------------------------------------------------------------------
// launch
// ---------------------------------------------------------------------------
extern "C" void kernel_launch(void* const* d_in, const int* in_sizes, int n_in,
                              void* d_out, int out_size) {
    const float* v      = (const float*)d_in[0];
    const float* q      = (const float*)d_in[1];
    const float* w_v4q  = (const float*)d_in[2];
    const float* b_v4q  = (const float*)d_in[3];
    const float* w_q4v  = (const float*)d_in[4];
    const float* b_q4v  = (const float*)d_in[5];
    const float* w_vlin = (const float*)d_in[6];
    const float* b_vlin = (const float*)d_in[7];
    const float* w_qlin = (const float*)d_in[8];
    const float* b_qlin = (const float*)d_in[9];
    const float* w_vout = (const float*)d_in[10];
    const float* b_vout = (const float*)d_in[11];
    const float* w_qout = (const float*)d_in[12];
    const float* b_qout = (const float*)d_in[13];

    float* out_v = (float*)d_out;
    float* out_q = out_v + (size_t)BATCH * NV * DMODEL;

    float *p_vmean, *p_qmean, *p_gv, *p_gq, *p_vtran, *p_qtran, *p_vupd, *p_qupd;
    cudaGetSymbolAddress((void**)&p_vmean, g_vmean);
    cudaGetSymbolAddress((void**)&p_qmean, g_qmean);
    cudaGetSymbolAddress((void**)&p_gv,    g_gate_v);
    cudaGetSymbolAddress((void**)&p_gq,    g_gate_q);
    cudaGetSymbolAddress((void**)&p_vtran, g_vtran);
    cudaGetSymbolAddress((void**)&p_qtran, g_qtran);
    cudaGetSymbolAddress((void**)&p_vupd,  g_vupd);
    cudaGetSymbolAddress((void**)&p_qupd,  g_qupd);

    __half *Av_hi, *Av_lo, *Aq_hi, *Aq_lo, *Wvl_hi, *Wql_hi, *Wvo_hi, *Wqo_hi;
    cudaGetSymbolAddress((void**)&Av_hi, g_Av_hi);
    cudaGetSymbolAddress((void**)&Av_lo, g_Av_lo);
    cudaGetSymbolAddress((void**)&Aq_hi, g_Aq_hi);
    cudaGetSymbolAddress((void**)&Aq_lo, g_Aq_lo);
    cudaGetSymbolAddress((void**)&Wvl_hi, g_Wvl_hi);
    cudaGetSymbolAddress((void**)&Wql_hi, g_Wql_hi);
    cudaGetSymbolAddress((void**)&Wvo_hi, g_Wvo_hi);
    cudaGetSymbolAddress((void**)&Wqo_hi, g_Wqo_hi);

    const int SMEM_G = 3 * GSTAGE;   // 87552
    cudaFuncSetAttribute(bmma_gemm<true>,  cudaFuncAttributeMaxDynamicSharedMemorySize, SMEM_G);
    cudaFuncSetAttribute(bmma_gemm<false>, cudaFuncAttributeMaxDynamicSharedMemorySize, SMEM_G);

    const int smemV = (16 * 132 + 64 * 132 + 16 * (512 + 4) + 16) * (int)sizeof(float);
    const int smemQ = (16 * 132 + 64 * 132 + 16 * (256 + 4) + 16) * (int)sizeof(float);
    cudaFuncSetAttribute(attn_kernel<512, NV>, cudaFuncAttributeMaxDynamicSharedMemorySize, smemV);
    cudaFuncSetAttribute(attn_kernel<256, NQ>, cudaFuncAttributeMaxDynamicSharedMemorySize, smemQ);

    // means + gates
    mean_kernel<<<dim3(BATCH, 4), 256>>>(v, p_vmean, NV);
    mean_kernel<<<dim3(BATCH, 4), 256>>>(q, p_qmean, NQ);
    gate_kernel<<<dim3(BATCH, 8), 512>>>(p_vmean, w_v4q, b_v4q, p_gq);
    gate_kernel<<<dim3(BATCH, 8), 512>>>(p_qmean, w_q4v, b_q4v, p_gv);

    // operand conversions
    const int nAv = BATCH * NV * DMODEL, nAq = BATCH * NQ * DMODEL;
    const int nWl = DMODEL * D3, nWo = DMODEL * DMODEL;
    split2_kernel<<<nAv / 1024, 256>>>(v, Av_hi, Av_lo, nAv);
    split2_kernel<<<nAq / 1024, 256>>>(q, Aq_hi, Aq_lo, nAq);
    tohalf_kernel<<<nWl / 1024, 256>>>(w_vlin, Wvl_hi, nWl);
    tohalf_kernel<<<nWl / 1024, 256>>>(w_qlin, Wql_hi, nWl);
    tohalf_kernel<<<nWo / 1024, 256>>>(w_vout, Wvo_hi, nWo);
    tohalf_kernel<<<nWo / 1024, 256>>>(w_qout, Wqo_hi, nWo);

    // gated tran projections
    bmma_gemm<true><<<dim3(D3 / 128, BATCH * NV / 128), 256, SMEM_G>>>(
        Av_hi, Av_lo, Wvl_hi, b_vlin, p_gv, p_vtran, BATCH * NV, D3, DMODEL, NV);
    bmma_gemm<true><<<dim3(D3 / 128, BATCH * NQ / 128), 256, SMEM_G>>>(
        Aq_hi, Aq_lo, Wql_hi, b_qlin, p_gq, p_qtran, BATCH * NQ, D3, DMODEL, NQ);

    // attention
    attn_kernel<512, NV><<<dim3(NV / 16, NHEAD, BATCH), 128, smemV>>>(p_vtran, p_vupd);
    attn_kernel<256, NQ><<<dim3(NQ / 16, NHEAD, BATCH), 128, smemQ>>>(p_qtran, p_qupd);

    // residual add + split (reuse A buffers)
    addsplit2_kernel<<<nAv / 1024, 256>>>(v, p_vupd, Av_hi, Av_lo, nAv);
    addsplit2_kernel<<<nAq / 1024, 256>>>(q, p_qupd, Aq_hi, Aq_lo, nAq);

    // output projections
    bmma_gemm<false><<<dim3(DMODEL / 128, BATCH * NV / 128), 256, SMEM_G>>>(
        Av_hi, Av_lo, Wvo_hi, b_vout, nullptr, out_v, BATCH * NV, DMODEL, DMODEL, NV);
    bmma_gemm<false><<<dim3(DMODEL / 128, BATCH * NQ / 128), 256, SMEM_G>>>(
        Aq_hi, Aq_lo, Wqo_hi, b_qout, nullptr, out_q, BATCH * NQ, DMODEL, DMODEL, NQ);
}

// round 8
// speedup vs baseline: 8.1799x; 3.4196x over previous
#include <cuda_runtime.h>
#include <cuda_fp16.h>
#include <math.h>
#include <stdint.h>

// Problem constants
#define BATCH 32
#define NV    512
#define NQ    256
#define DMODEL 1024
#define D3    3072
#define NHEAD 8
#define DH    128

// ---------------------------------------------------------------------------
// Scratch (static device globals — allocation-free per harness rules)
// ---------------------------------------------------------------------------
__device__ float g_vmean[BATCH * DMODEL];
__device__ float g_qmean[BATCH * DMODEL];
__device__ float g_gate_v[BATCH * DMODEL];
__device__ float g_gate_q[BATCH * DMODEL];
__device__ float g_vupd[BATCH * NV * DMODEL];
__device__ float g_qupd[BATCH * NQ * DMODEL];
// fp16 tran buffers (output of gated projections, input of attention)
__device__ __half g_vtran_h[BATCH * NV * D3];
__device__ __half g_qtran_h[BATCH * NQ * D3];
// fp16 split operand buffers (A: hi+lo, W: hi only)
__device__ __half g_Av_hi[BATCH * NV * DMODEL];
__device__ __half g_Av_lo[BATCH * NV * DMODEL];
__device__ __half g_Aq_hi[BATCH * NQ * DMODEL];
__device__ __half g_Aq_lo[BATCH * NQ * DMODEL];
__device__ __half g_Wvl_hi[DMODEL * D3];
__device__ __half g_Wql_hi[DMODEL * D3];
__device__ __half g_Wvo_hi[DMODEL * DMODEL];
__device__ __half g_Wqo_hi[DMODEL * DMODEL];

// ---------------------------------------------------------------------------
// PTX helpers
// ---------------------------------------------------------------------------
__device__ __forceinline__ uint32_t smem_u32(const void* p) {
    uint32_t a;
    asm("{ .reg .u64 t; cvta.to.shared.u64 t, %1; cvt.u32.u64 %0, t; }" : "=r"(a) : "l"(p));
    return a;
}
__device__ __forceinline__ void cp_async16(uint32_t dst, const void* src) {
    asm volatile("cp.async.cg.shared.global [%0], [%1], 16;" :: "r"(dst), "l"(src));
}
#define CP_COMMIT() asm volatile("cp.async.commit_group;" ::: "memory")
#define CP_WAIT(n)  asm volatile("cp.async.wait_group %0;" :: "n"(n) : "memory")

__device__ __forceinline__ void ldsm_x4(uint32_t* d, uint32_t addr) {
    asm volatile("ldmatrix.sync.aligned.m8n8.x4.shared.b16 {%0,%1,%2,%3}, [%4];"
                 : "=r"(d[0]), "=r"(d[1]), "=r"(d[2]), "=r"(d[3]) : "r"(addr));
}
__device__ __forceinline__ void ldsm_x4_t(uint32_t* d, uint32_t addr) {
    asm volatile("ldmatrix.sync.aligned.m8n8.x4.trans.shared.b16 {%0,%1,%2,%3}, [%4];"
                 : "=r"(d[0]), "=r"(d[1]), "=r"(d[2]), "=r"(d[3]) : "r"(addr));
}
__device__ __forceinline__ void mma_f16(float* c, const uint32_t* a, const uint32_t* b) {
    asm volatile(
        "mma.sync.aligned.m16n8k16.row.col.f32.f16.f16.f32 "
        "{%0,%1,%2,%3}, {%4,%5,%6,%7}, {%8,%9}, {%0,%1,%2,%3};"
        : "+f"(c[0]), "+f"(c[1]), "+f"(c[2]), "+f"(c[3])
        : "r"(a[0]), "r"(a[1]), "r"(a[2]), "r"(a[3]), "r"(b[0]), "r"(b[1]));
}

__device__ __forceinline__ void store_pair(float* p, float x, float y) {
    *(float2*)p = make_float2(x, y);
}
__device__ __forceinline__ void store_pair(__half* p, float x, float y) {
    *(__half2*)p = __floats2half2_rn(x, y);
}

// ---------------------------------------------------------------------------
// Elementwise conversion kernels
// ---------------------------------------------------------------------------
__global__ void split2_kernel(const float* __restrict__ x, __half* __restrict__ hi,
                              __half* __restrict__ lo, int n) {
    int i = (blockIdx.x * 256 + threadIdx.x) * 4;
    if (i >= n) return;
    float4 v = *(const float4*)(x + i);
    __half h0 = __float2half_rn(v.x), h1 = __float2half_rn(v.y);
    __half h2 = __float2half_rn(v.z), h3 = __float2half_rn(v.w);
    __half l0 = __float2half_rn(v.x - __half2float(h0));
    __half l1 = __float2half_rn(v.y - __half2float(h1));
    __half l2 = __float2half_rn(v.z - __half2float(h2));
    __half l3 = __float2half_rn(v.w - __half2float(h3));
    *(__half2*)(hi + i)     = __half2(h0, h1);
    *(__half2*)(hi + i + 2) = __half2(h2, h3);
    *(__half2*)(lo + i)     = __half2(l0, l1);
    *(__half2*)(lo + i + 2) = __half2(l2, l3);
}

__global__ void addsplit2_kernel(const float* __restrict__ x, const float* __restrict__ y,
                                 __half* __restrict__ hi, __half* __restrict__ lo, int n) {
    int i = (blockIdx.x * 256 + threadIdx.x) * 4;
    if (i >= n) return;
    float4 a = *(const float4*)(x + i);
    float4 b = *(const float4*)(y + i);
    a.x += b.x; a.y += b.y; a.z += b.z; a.w += b.w;
    __half h0 = __float2half_rn(a.x), h1 = __float2half_rn(a.y);
    __half h2 = __float2half_rn(a.z), h3 = __float2half_rn(a.w);
    __half l0 = __float2half_rn(a.x - __half2float(h0));
    __half l1 = __float2half_rn(a.y - __half2float(h1));
    __half l2 = __float2half_rn(a.z - __half2float(h2));
    __half l3 = __float2half_rn(a.w - __half2float(h3));
    *(__half2*)(hi + i)     = __half2(h0, h1);
    *(__half2*)(hi + i + 2) = __half2(h2, h3);
    *(__half2*)(lo + i)     = __half2(l0, l1);
    *(__half2*)(lo + i + 2) = __half2(l2, l3);
}

__global__ void tohalf_kernel(const float* __restrict__ x, __half* __restrict__ hi, int n) {
    int i = (blockIdx.x * 256 + threadIdx.x) * 4;
    if (i >= n) return;
    float4 v = *(const float4*)(x + i);
    *(__half2*)(hi + i)     = __half2(__float2half_rn(v.x), __float2half_rn(v.y));
    *(__half2*)(hi + i + 2) = __half2(__float2half_rn(v.z), __float2half_rn(v.w));
}

// ---------------------------------------------------------------------------
// Row means
// ---------------------------------------------------------------------------
__global__ void mean_kernel(const float* __restrict__ x, float* __restrict__ out, int nrows) {
    int b = blockIdx.x;
    int d = blockIdx.y * 256 + threadIdx.x;
    const float* p = x + (size_t)b * nrows * DMODEL + d;
    float s0 = 0.f, s1 = 0.f, s2 = 0.f, s3 = 0.f;
    for (int n = 0; n < nrows; n += 4) {
        s0 += p[(size_t)(n + 0) * DMODEL];
        s1 += p[(size_t)(n + 1) * DMODEL];
        s2 += p[(size_t)(n + 2) * DMODEL];
        s3 += p[(size_t)(n + 3) * DMODEL];
    }
    out[b * DMODEL + d] = (s0 + s1 + s2 + s3) / (float)nrows;
}

// ---------------------------------------------------------------------------
// Gates: k-split 4 ways across 512 threads, smem reduce
// ---------------------------------------------------------------------------
__global__ __launch_bounds__(512)
void gate_kernel(const float* __restrict__ mean, const float* __restrict__ W,
                 const float* __restrict__ bias, float* __restrict__ gate) {
    __shared__ float sm[DMODEL];
    __shared__ float part[4][128];
    const int b = blockIdx.x;
    const int l = threadIdx.x & 127;
    const int ks = threadIdx.x >> 7;
    const int d = blockIdx.y * 128 + l;
    for (int i = threadIdx.x; i < DMODEL; i += 512) sm[i] = mean[b * DMODEL + i];
    __syncthreads();
    const int k0 = ks * 256;
    float a0 = 0.f, a1 = 0.f, a2 = 0.f, a3 = 0.f;
#pragma unroll 4
    for (int k = 0; k < 256; k += 4) {
        a0 += sm[k0 + k + 0] * __ldg(&W[(size_t)(k0 + k + 0) * DMODEL + d]);
        a1 += sm[k0 + k + 1] * __ldg(&W[(size_t)(k0 + k + 1) * DMODEL + d]);
        a2 += sm[k0 + k + 2] * __ldg(&W[(size_t)(k0 + k + 2) * DMODEL + d]);
        a3 += sm[k0 + k + 3] * __ldg(&W[(size_t)(k0 + k + 3) * DMODEL + d]);
    }
    part[ks][l] = (a0 + a1) + (a2 + a3);
    __syncthreads();
    if (ks == 0) {
        float acc = part[0][l] + part[1][l] + part[2][l] + part[3][l] + bias[d];
        gate[b * DMODEL + d] = 1.0f + 1.0f / (1.0f + __expf(-acc));
    }
}

// ---------------------------------------------------------------------------
// Split-fp16 2-pass mma GEMM.  C[M,N] = epi( (Ah+Al) @ Wh + bias )
// CTA 128x128, BK=32, 256 threads, warp tile 32x64. 3-stage cp.async pipeline.
// ---------------------------------------------------------------------------
#define GSTAGE 29184
#define GOFF_AL 10240
#define GOFF_BH 20480

template <bool GATE, typename OUT>
__global__ __launch_bounds__(256)
void bmma_gemm(const __half* __restrict__ Ahi, const __half* __restrict__ Alo,
               const __half* __restrict__ Bhi,
               const float* __restrict__ bias, const float* __restrict__ gate,
               OUT* __restrict__ C, int M, int N, int K, int rows_per_batch) {
    extern __shared__ __align__(16) char smem[];
    const uint32_t sb = smem_u32(smem);
    const int tid = threadIdx.x;
    const int warp = tid >> 5, lane = tid & 31;
    const int wm = warp & 3, wn = warp >> 2;
    const int m0 = blockIdx.y * 128, n0 = blockIdx.x * 128;
    const int NST = K >> 5;

    auto load_stage = [&](int s) {
        const uint32_t buf = sb + (uint32_t)(s % 3) * GSTAGE;
        const int k0 = s * 32;
#pragma unroll
        for (int i = 0; i < 2; i++) {
            int c = tid + i * 256;
            {
                int row = c >> 2, kc = c & 3;
                size_t g = (size_t)(m0 + row) * K + k0 + kc * 8;
                uint32_t d = buf + (uint32_t)(row * 80 + kc * 16);
                cp_async16(d, Ahi + g);
                cp_async16(d + GOFF_AL, Alo + g);
            }
            {
                int row = c >> 4, nc = c & 15;
                size_t g = (size_t)(k0 + row) * N + n0 + nc * 8;
                cp_async16(buf + GOFF_BH + (uint32_t)(row * 272 + nc * 16), Bhi + g);
            }
        }
    };

    float acc[2][8][4];
#pragma unroll
    for (int i = 0; i < 2; i++)
#pragma unroll
        for (int j = 0; j < 8; j++)
#pragma unroll
            for (int t = 0; t < 4; t++) acc[i][j][t] = 0.f;

    load_stage(0); CP_COMMIT();
    load_stage(1); CP_COMMIT();

    const int lr = lane & 15;
    const int lc = lane >> 4;
    for (int s = 0; s < NST; s++) {
        if (s + 1 < NST) { CP_WAIT(1); } else { CP_WAIT(0); }
        __syncthreads();
        const uint32_t buf = sb + (uint32_t)(s % 3) * GSTAGE;
#pragma unroll
        for (int ks = 0; ks < 2; ks++) {
            uint32_t ah[2][4], al[2][4];
#pragma unroll
            for (int mi = 0; mi < 2; mi++) {
                uint32_t addr = buf + (uint32_t)((wm * 32 + mi * 16 + lr) * 80 + ks * 32 + lc * 16);
                ldsm_x4(ah[mi], addr);
                ldsm_x4(al[mi], addr + GOFF_AL);
            }
            uint32_t bh[8][2];
#pragma unroll
            for (int nio = 0; nio < 4; nio++) {
                uint32_t addr = buf + GOFF_BH +
                    (uint32_t)((ks * 16 + lr) * 272 + wn * 128 + nio * 32 + lc * 16);
                uint32_t t4[4];
                ldsm_x4_t(t4, addr);
                bh[nio * 2][0] = t4[0]; bh[nio * 2][1] = t4[1];
                bh[nio * 2 + 1][0] = t4[2]; bh[nio * 2 + 1][1] = t4[3];
            }
#pragma unroll
            for (int mi = 0; mi < 2; mi++)
#pragma unroll
                for (int ni = 0; ni < 8; ni++) {
                    mma_f16(acc[mi][ni], ah[mi], bh[ni]);
                    mma_f16(acc[mi][ni], al[mi], bh[ni]);
                }
        }
        if (s + 2 < NST) { load_stage(s + 2); CP_COMMIT(); }
    }

    const int gid = lane >> 2, tig = lane & 3;
    const int b_idx = GATE ? (m0 / rows_per_batch) : 0;
#pragma unroll
    for (int mi = 0; mi < 2; mi++) {
        int r = m0 + wm * 32 + mi * 16 + gid;
#pragma unroll
        for (int ni = 0; ni < 8; ni++) {
            int c = n0 + wn * 64 + ni * 8 + tig * 2;
            float g0 = 1.f, g1 = 1.f;
            if (GATE) {
                g0 = gate[b_idx * DMODEL + (c & (DMODEL - 1))];
                g1 = gate[b_idx * DMODEL + ((c + 1) & (DMODEL - 1))];
            }
            float bz0 = bias[c], bz1 = bias[c + 1];
            store_pair(&C[(size_t)r * N + c],
                       fmaxf(acc[mi][ni][0] + bz0, 0.f) * g0,
                       fmaxf(acc[mi][ni][1] + bz1, 0.f) * g1);
            store_pair(&C[(size_t)(r + 8) * N + c],
                       fmaxf(acc[mi][ni][2] + bz0, 0.f) * g0,
                       fmaxf(acc[mi][ni][3] + bz1, 0.f) * g1);
        }
    }
}

// ---------------------------------------------------------------------------
// fp16 tensor-core attention. Block: 32 q-rows x (b,h). 128 threads, 4 warps.
// Full logits row in smem (fp16), two-phase (QK^T+softmax, then PV).
// tran layout: [B, NROWS, 3072] halves; key +0, query +1024, val +2048.
// ---------------------------------------------------------------------------
template <int NK, int NROWS>
__global__ __launch_bounds__(128)
void attn16(const __half* __restrict__ tran, float* __restrict__ upd) {
    constexpr int NC = NK / 64;            // 64-row K/V chunks
    constexpr int QSB = 272;               // 136 halves row stride (bytes)
    constexpr int PSH = NK + 8;            // logits row stride (halves)
    constexpr int OFF_KVB = 32 * QSB;                  // 8704
    constexpr int KVBUF = 64 * QSB;                    // 17408
    constexpr int OFF_PSB = OFF_KVB + 2 * KVBUF;       // 43520
    constexpr int OFF_RINV = OFF_PSB + 32 * PSH * 2;

    extern __shared__ __align__(16) char smem[];
    const uint32_t sb = smem_u32(smem);
    __half* smh = (__half*)smem;
    float* rinv = (float*)(smem + OFF_RINV);

    const int tid = threadIdx.x;
    const int wid = tid >> 5, lane = tid & 31;
    const int lr = lane & 15, lc = lane >> 4;
    const int gid = lane >> 2, tig = lane & 3;
    const int q0 = blockIdx.x * 32, h = blockIdx.y, b = blockIdx.z;

    auto ldQ = [&]() {
#pragma unroll
        for (int i = 0; i < 4; i++) {
            int c = tid + i * 128;
            int row = c >> 4, ch = c & 15;
            cp_async16(sb + (uint32_t)(row * QSB + ch * 16),
                       tran + ((size_t)(b * NROWS + q0 + row) * D3 + DMODEL + h * DH + ch * 8));
        }
    };
    auto ldKV = [&](int part, int chunk, int buf) {
#pragma unroll
        for (int i = 0; i < 8; i++) {
            int c = tid + i * 128;
            int row = c >> 4, ch = c & 15;
            cp_async16(sb + OFF_KVB + (uint32_t)(buf * KVBUF + row * QSB + ch * 16),
                       tran + ((size_t)(b * NROWS + chunk * 64 + row) * D3 + part + h * DH + ch * 8));
        }
    };

    // ---------------- phase 1: logits ----------------
    ldQ(); ldKV(0, 0, 0); CP_COMMIT();
    for (int c = 0; c < NC; c++) {
        if (c + 1 < NC) { ldKV(0, c + 1, (c + 1) & 1); CP_COMMIT(); CP_WAIT(1); }
        else           { CP_WAIT(0); }
        __syncthreads();
        const uint32_t kb = sb + OFF_KVB + (uint32_t)((c & 1) * KVBUF);
        float acc[2][2][4];
#pragma unroll
        for (int mi = 0; mi < 2; mi++)
#pragma unroll
            for (int ni = 0; ni < 2; ni++)
#pragma unroll
                for (int t = 0; t < 4; t++) acc[mi][ni][t] = 0.f;
#pragma unroll
        for (int ks = 0; ks < 8; ks++) {
            uint32_t a[2][4];
            ldsm_x4(a[0], sb + (uint32_t)(lr * QSB + ks * 32 + lc * 16));
            ldsm_x4(a[1], sb + (uint32_t)((16 + lr) * QSB + ks * 32 + lc * 16));
            uint32_t r4[4];
            ldsm_x4(r4, kb + (uint32_t)((wid * 16 + lr) * QSB + ks * 32 + lc * 16));
            uint32_t b0[2] = {r4[0], r4[2]}, b1[2] = {r4[1], r4[3]};
            mma_f16(acc[0][0], a[0], b0); mma_f16(acc[0][1], a[0], b1);
            mma_f16(acc[1][0], a[1], b0); mma_f16(acc[1][1], a[1], b1);
        }
        const float scl = 0.08838834764831845f;   // 1/sqrt(128)
#pragma unroll
        for (int mi = 0; mi < 2; mi++)
#pragma unroll
            for (int ni = 0; ni < 2; ni++) {
                int col = c * 64 + wid * 16 + ni * 8 + tig * 2;
                *(__half2*)(smh + (OFF_PSB / 2) + (mi * 16 + gid) * PSH + col) =
                    __floats2half2_rn(acc[mi][ni][0] * scl, acc[mi][ni][1] * scl);
                *(__half2*)(smh + (OFF_PSB / 2) + (mi * 16 + gid + 8) * PSH + col) =
                    __floats2half2_rn(acc[mi][ni][2] * scl, acc[mi][ni][3] * scl);
            }
        __syncthreads();
    }

    // kick off V chunk 0 (overlaps softmax)
    ldKV(2 * DMODEL, 0, 0); CP_COMMIT();

    // ---------------- phase 2: softmax ----------------
    {
        const int row = tid >> 2, g = tid & 3;
        __half2* pr = (__half2*)(smh + (OFF_PSB / 2) + row * PSH);
        float m = -1e30f;
        for (int i = g; i < NK / 2; i += 4) {
            float2 f = __half22float2(pr[i]);
            m = fmaxf(m, fmaxf(f.x, f.y));
        }
        m = fmaxf(m, __shfl_xor_sync(0xffffffffu, m, 1));
        m = fmaxf(m, __shfl_xor_sync(0xffffffffu, m, 2));
        float s = 0.f;
        for (int i = g; i < NK / 2; i += 4) {
            float2 f = __half22float2(pr[i]);
            float e0 = __expf(f.x - m), e1 = __expf(f.y - m);
            s += e0 + e1;
            pr[i] = __floats2half2_rn(e0, e1);
        }
        s += __shfl_xor_sync(0xffffffffu, s, 1);
        s += __shfl_xor_sync(0xffffffffu, s, 2);
        if (g == 0) rinv[row] = 1.0f / s;
    }

    // ---------------- phase 3: O = P @ V ----------------
    float acc[2][4][4];
#pragma unroll
    for (int mi = 0; mi < 2; mi++)
#pragma unroll
        for (int ni = 0; ni < 4; ni++)
#pragma unroll
            for (int t = 0; t < 4; t++) acc[mi][ni][t] = 0.f;

    for (int c = 0; c < NC; c++) {
        if (c + 1 < NC) { ldKV(2 * DMODEL, c + 1, (c + 1) & 1); CP_COMMIT(); CP_WAIT(1); }
        else           { CP_WAIT(0); }
        __syncthreads();
        const uint32_t kb = sb + OFF_KVB + (uint32_t)((c & 1) * KVBUF);
#pragma unroll
        for (int ks = 0; ks < 4; ks++) {
            uint32_t a[2][4];
            ldsm_x4(a[0], sb + OFF_PSB + (uint32_t)(lr * PSH * 2 + (c * 64 + ks * 16 + lc * 8) * 2));
            ldsm_x4(a[1], sb + OFF_PSB + (uint32_t)((16 + lr) * PSH * 2 + (c * 64 + ks * 16 + lc * 8) * 2));
            uint32_t bv[4][2];
#pragma unroll
            for (int nio = 0; nio < 2; nio++) {
                uint32_t t4[4];
                ldsm_x4_t(t4, kb + (uint32_t)((ks * 16 + lr) * QSB + wid * 64 + nio * 32 + lc * 16));
                bv[nio * 2][0] = t4[0]; bv[nio * 2][1] = t4[1];
                bv[nio * 2 + 1][0] = t4[2]; bv[nio * 2 + 1][1] = t4[3];
            }
#pragma unroll
            for (int mi = 0; mi < 2; mi++)
#pragma unroll
                for (int ni = 0; ni < 4; ni++)
                    mma_f16(acc[mi][ni], a[mi], bv[ni]);
        }
        __syncthreads();
    }

    // epilogue: normalize and write fp32
#pragma unroll
    for (int mi = 0; mi < 2; mi++) {
        int r0 = mi * 16 + gid, r1 = r0 + 8;
        float inv0 = rinv[r0], inv1 = rinv[r1];
#pragma unroll
        for (int ni = 0; ni < 4; ni++) {
            int col = h * DH + wid * 32 + ni * 8 + tig * 2;
            *(float2*)&upd[(size_t)(b * NROWS + q0 + r0) * DMODEL + col] =
                make_float2(acc[mi][ni][0] * inv0, acc[mi][ni][1] * inv0);
            *(float2*)&upd[(size_t)(b * NROWS + q0 + r1) * DMODEL + col] =
                make_float2(acc[mi][ni][2] * inv1, acc[mi][ni][3] * inv1);
        }
    }
}

// ---------------------------------------------------------------------------
// launch
// ---------------------------------------------------------------------------
extern "C" void kernel_launch(void* const* d_in, const int* in_sizes, int n_in,
                              void* d_out, int out_size) {
    const float* v      = (const float*)d_in[0];
    const float* q      = (const float*)d_in[1];
    const float* w_v4q  = (const float*)d_in[2];
    const float* b_v4q  = (const float*)d_in[3];
    const float* w_q4v  = (const float*)d_in[4];
    const float* b_q4v  = (const float*)d_in[5];
    const float* w_vlin = (const float*)d_in[6];
    const float* b_vlin = (const float*)d_in[7];
    const float* w_qlin = (const float*)d_in[8];
    const float* b_qlin = (const float*)d_in[9];
    const float* w_vout = (const float*)d_in[10];
    const float* b_vout = (const float*)d_in[11];
    const float* w_qout = (const float*)d_in[12];
    const float* b_qout = (const float*)d_in[13];

    float* out_v = (float*)d_out;
    float* out_q = out_v + (size_t)BATCH * NV * DMODEL;

    float *p_vmean, *p_qmean, *p_gv, *p_gq, *p_vupd, *p_qupd;
    cudaGetSymbolAddress((void**)&p_vmean, g_vmean);
    cudaGetSymbolAddress((void**)&p_qmean, g_qmean);
    cudaGetSymbolAddress((void**)&p_gv,    g_gate_v);
    cudaGetSymbolAddress((void**)&p_gq,    g_gate_q);
    cudaGetSymbolAddress((void**)&p_vupd,  g_vupd);
    cudaGetSymbolAddress((void**)&p_qupd,  g_qupd);

    __half *vtran, *qtran;
    cudaGetSymbolAddress((void**)&vtran, g_vtran_h);
    cudaGetSymbolAddress((void**)&qtran, g_qtran_h);

    __half *Av_hi, *Av_lo, *Aq_hi, *Aq_lo, *Wvl_hi, *Wql_hi, *Wvo_hi, *Wqo_hi;
    cudaGetSymbolAddress((void**)&Av_hi, g_Av_hi);
    cudaGetSymbolAddress((void**)&Av_lo, g_Av_lo);
    cudaGetSymbolAddress((void**)&Aq_hi, g_Aq_hi);
    cudaGetSymbolAddress((void**)&Aq_lo, g_Aq_lo);
    cudaGetSymbolAddress((void**)&Wvl_hi, g_Wvl_hi);
    cudaGetSymbolAddress((void**)&Wql_hi, g_Wql_hi);
    cudaGetSymbolAddress((void**)&Wvo_hi, g_Wvo_hi);
    cudaGetSymbolAddress((void**)&Wqo_hi, g_Wqo_hi);

    const int SMEM_G = 3 * GSTAGE;
    cudaFuncSetAttribute((const void*)bmma_gemm<true, __half>, cudaFuncAttributeMaxDynamicSharedMemorySize, SMEM_G);
    cudaFuncSetAttribute((const void*)bmma_gemm<false, float>, cudaFuncAttributeMaxDynamicSharedMemorySize, SMEM_G);

    const int SMEM_AV = (32 * 272) + 2 * (64 * 272) + 32 * (512 + 8) * 2 + 128;
    const int SMEM_AQ = (32 * 272) + 2 * (64 * 272) + 32 * (256 + 8) * 2 + 128;
    cudaFuncSetAttribute((const void*)attn16<512, NV>, cudaFuncAttributeMaxDynamicSharedMemorySize, SMEM_AV);
    cudaFuncSetAttribute((const void*)attn16<256, NQ>, cudaFuncAttributeMaxDynamicSharedMemorySize, SMEM_AQ);

    // means + gates
    mean_kernel<<<dim3(BATCH, 4), 256>>>(v, p_vmean, NV);
    mean_kernel<<<dim3(BATCH, 4), 256>>>(q, p_qmean, NQ);
    gate_kernel<<<dim3(BATCH, 8), 512>>>(p_vmean, w_v4q, b_v4q, p_gq);
    gate_kernel<<<dim3(BATCH, 8), 512>>>(p_qmean, w_q4v, b_q4v, p_gv);

    // operand conversions
    const int nAv = BATCH * NV * DMODEL, nAq = BATCH * NQ * DMODEL;
    const int nWl = DMODEL * D3, nWo = DMODEL * DMODEL;
    split2_kernel<<<nAv / 1024, 256>>>(v, Av_hi, Av_lo, nAv);
    split2_kernel<<<nAq / 1024, 256>>>(q, Aq_hi, Aq_lo, nAq);
    tohalf_kernel<<<nWl / 1024, 256>>>(w_vlin, Wvl_hi, nWl);
    tohalf_kernel<<<nWl / 1024, 256>>>(w_qlin, Wql_hi, nWl);
    tohalf_kernel<<<nWo / 1024, 256>>>(w_vout, Wvo_hi, nWo);
    tohalf_kernel<<<nWo / 1024, 256>>>(w_qout, Wqo_hi, nWo);

    // gated tran projections -> fp16 tran
    bmma_gemm<true, __half><<<dim3(D3 / 128, BATCH * NV / 128), 256, SMEM_G>>>(
        Av_hi, Av_lo, Wvl_hi, b_vlin, p_gv, vtran, BATCH * NV, D3, DMODEL, NV);
    bmma_gemm<true, __half><<<dim3(D3 / 128, BATCH * NQ / 128), 256, SMEM_G>>>(
        Aq_hi, Aq_lo, Wql_hi, b_qlin, p_gq, qtran, BATCH * NQ, D3, DMODEL, NQ);

    // tensor-core attention
    attn16<512, NV><<<dim3(NV / 32, NHEAD, BATCH), 128, SMEM_AV>>>(vtran, p_vupd);
    attn16<256, NQ><<<dim3(NQ / 32, NHEAD, BATCH), 128, SMEM_AQ>>>(qtran, p_qupd);

    // residual add + split (reuse A buffers)
    addsplit2_kernel<<<nAv / 1024, 256>>>(v, p_vupd, Av_hi, Av_lo, nAv);
    addsplit2_kernel<<<nAq / 1024, 256>>>(q, p_qupd, Aq_hi, Aq_lo, nAq);

    // output projections
    bmma_gemm<false, float><<<dim3(DMODEL / 128, BATCH * NV / 128), 256, SMEM_G>>>(
        Av_hi, Av_lo, Wvo_hi, b_vout, nullptr, out_v, BATCH * NV, DMODEL, DMODEL, NV);
    bmma_gemm<false, float><<<dim3(DMODEL / 128, BATCH * NQ / 128), 256, SMEM_G>>>(
        Aq_hi, Aq_lo, Wqo_hi, b_qout, nullptr, out_q, BATCH * NQ, DMODEL, DMODEL, NQ);
}

// round 10
// speedup vs baseline: 11.2638x; 1.3770x over previous
#include <cuda_runtime.h>
#include <cuda_fp16.h>
#include <math.h>
#include <stdint.h>

// Problem constants
#define BATCH 32
#define NV    512
#define NQ    256
#define DMODEL 1024
#define D3    3072
#define NHEAD 8
#define DH    128

// ---------------------------------------------------------------------------
// Scratch (static device globals — allocation-free per harness rules)
// ---------------------------------------------------------------------------
__device__ float g_vmean[BATCH * DMODEL];
__device__ float g_qmean[BATCH * DMODEL];
__device__ float g_gate_v[BATCH * DMODEL];
__device__ float g_gate_q[BATCH * DMODEL];
// fp16 tran buffers (output of gated projections, input of attention)
__device__ __half g_vtran_h[BATCH * NV * D3];
__device__ __half g_qtran_h[BATCH * NQ * D3];
// fp16 operand buffers; A buffers are reused: half(v) before attention,
// half(v + v_update) after (attention epilogue writes them)
__device__ __half g_Av[BATCH * NV * DMODEL];
__device__ __half g_Aq[BATCH * NQ * DMODEL];
__device__ __half g_Wvl[DMODEL * D3];
__device__ __half g_Wql[DMODEL * D3];
__device__ __half g_Wvo[DMODEL * DMODEL];
__device__ __half g_Wqo[DMODEL * DMODEL];

// ---------------------------------------------------------------------------
// PTX helpers
// ---------------------------------------------------------------------------
__device__ __forceinline__ uint32_t smem_u32(const void* p) {
    uint32_t a;
    asm("{ .reg .u64 t; cvta.to.shared.u64 t, %1; cvt.u32.u64 %0, t; }" : "=r"(a) : "l"(p));
    return a;
}
__device__ __forceinline__ void cp_async16(uint32_t dst, const void* src) {
    asm volatile("cp.async.cg.shared.global [%0], [%1], 16;" :: "r"(dst), "l"(src));
}
#define CP_COMMIT() asm volatile("cp.async.commit_group;" ::: "memory")
#define CP_WAIT(n)  asm volatile("cp.async.wait_group %0;" :: "n"(n) : "memory")

__device__ __forceinline__ void ldsm_x4(uint32_t* d, uint32_t addr) {
    asm volatile("ldmatrix.sync.aligned.m8n8.x4.shared.b16 {%0,%1,%2,%3}, [%4];"
                 : "=r"(d[0]), "=r"(d[1]), "=r"(d[2]), "=r"(d[3]) : "r"(addr));
}
__device__ __forceinline__ void ldsm_x4_t(uint32_t* d, uint32_t addr) {
    asm volatile("ldmatrix.sync.aligned.m8n8.x4.trans.shared.b16 {%0,%1,%2,%3}, [%4];"
                 : "=r"(d[0]), "=r"(d[1]), "=r"(d[2]), "=r"(d[3]) : "r"(addr));
}
__device__ __forceinline__ void mma_f16(float* c, const uint32_t* a, const uint32_t* b) {
    asm volatile(
        "mma.sync.aligned.m16n8k16.row.col.f32.f16.f16.f32 "
        "{%0,%1,%2,%3}, {%4,%5,%6,%7}, {%8,%9}, {%0,%1,%2,%3};"
        : "+f"(c[0]), "+f"(c[1]), "+f"(c[2]), "+f"(c[3])
        : "r"(a[0]), "r"(a[1]), "r"(a[2]), "r"(a[3]), "r"(b[0]), "r"(b[1]));
}

__device__ __forceinline__ void store_pair(float* p, float x, float y) {
    *(float2*)p = make_float2(x, y);
}
__device__ __forceinline__ void store_pair(__half* p, float x, float y) {
    *(__half2*)p = __floats2half2_rn(x, y);
}

// ---------------------------------------------------------------------------
// fp32 -> fp16 conversion
// ---------------------------------------------------------------------------
__global__ void tohalf_kernel(const float* __restrict__ x, __half* __restrict__ hi, int n) {
    int i = (blockIdx.x * 256 + threadIdx.x) * 4;
    if (i >= n) return;
    float4 v = *(const float4*)(x + i);
    *(__half2*)(hi + i)     = __half2(__float2half_rn(v.x), __float2half_rn(v.y));
    *(__half2*)(hi + i + 2) = __half2(__float2half_rn(v.z), __float2half_rn(v.w));
}

// ---------------------------------------------------------------------------
// Row means
// ---------------------------------------------------------------------------
__global__ void mean_kernel(const float* __restrict__ x, float* __restrict__ out, int nrows) {
    int b = blockIdx.x;
    int d = blockIdx.y * 256 + threadIdx.x;
    const float* p = x + (size_t)b * nrows * DMODEL + d;
    float s0 = 0.f, s1 = 0.f, s2 = 0.f, s3 = 0.f;
    for (int n = 0; n < nrows; n += 4) {
        s0 += p[(size_t)(n + 0) * DMODEL];
        s1 += p[(size_t)(n + 1) * DMODEL];
        s2 += p[(size_t)(n + 2) * DMODEL];
        s3 += p[(size_t)(n + 3) * DMODEL];
    }
    out[b * DMODEL + d] = (s0 + s1 + s2 + s3) / (float)nrows;
}

// ---------------------------------------------------------------------------
// Gates: k-split 4 ways across 512 threads, smem reduce
// ---------------------------------------------------------------------------
__global__ __launch_bounds__(512)
void gate_kernel(const float* __restrict__ mean, const float* __restrict__ W,
                 const float* __restrict__ bias, float* __restrict__ gate) {
    __shared__ float sm[DMODEL];
    __shared__ float part[4][128];
    const int b = blockIdx.x;
    const int l = threadIdx.x & 127;
    const int ks = threadIdx.x >> 7;
    const int d = blockIdx.y * 128 + l;
    for (int i = threadIdx.x; i < DMODEL; i += 512) sm[i] = mean[b * DMODEL + i];
    __syncthreads();
    const int k0 = ks * 256;
    float a0 = 0.f, a1 = 0.f, a2 = 0.f, a3 = 0.f;
#pragma unroll 4
    for (int k = 0; k < 256; k += 4) {
        a0 += sm[k0 + k + 0] * __ldg(&W[(size_t)(k0 + k + 0) * DMODEL + d]);
        a1 += sm[k0 + k + 1] * __ldg(&W[(size_t)(k0 + k + 1) * DMODEL + d]);
        a2 += sm[k0 + k + 2] * __ldg(&W[(size_t)(k0 + k + 2) * DMODEL + d]);
        a3 += sm[k0 + k + 3] * __ldg(&W[(size_t)(k0 + k + 3) * DMODEL + d]);
    }
    part[ks][l] = (a0 + a1) + (a2 + a3);
    __syncthreads();
    if (ks == 0) {
        float acc = part[0][l] + part[1][l] + part[2][l] + part[3][l] + bias[d];
        gate[b * DMODEL + d] = 1.0f + 1.0f / (1.0f + __expf(-acc));
    }
}

// ---------------------------------------------------------------------------
// Single-pass fp16 mma GEMM.  C[M,N] = epi( A @ W + bias )
// CTA 128x128, BK=32, 256 threads, warp tile 32x64. 3-stage cp.async pipeline.
// smem stage: A 128*80=10240 | B 32*272=8704 at +10240; stage 18944.
// ---------------------------------------------------------------------------
#define GSTAGE 18944
#define GOFF_B 10240

template <bool GATE, typename OUT>
__global__ __launch_bounds__(256)
void bmma_gemm(const __half* __restrict__ A, const __half* __restrict__ B,
               const float* __restrict__ bias, const float* __restrict__ gate,
               OUT* __restrict__ C, int M, int N, int K, int rows_per_batch) {
    extern __shared__ __align__(16) char smem[];
    const uint32_t sb = smem_u32(smem);
    const int tid = threadIdx.x;
    const int warp = tid >> 5, lane = tid & 31;
    const int wm = warp & 3, wn = warp >> 2;
    const int m0 = blockIdx.y * 128, n0 = blockIdx.x * 128;
    const int NST = K >> 5;

    auto load_stage = [&](int s) {
        const uint32_t buf = sb + (uint32_t)(s % 3) * GSTAGE;
        const int k0 = s * 32;
#pragma unroll
        for (int i = 0; i < 2; i++) {
            int c = tid + i * 256;
            {
                int row = c >> 2, kc = c & 3;
                cp_async16(buf + (uint32_t)(row * 80 + kc * 16),
                           A + ((size_t)(m0 + row) * K + k0 + kc * 8));
            }
            {
                int row = c >> 4, nc = c & 15;
                cp_async16(buf + GOFF_B + (uint32_t)(row * 272 + nc * 16),
                           B + ((size_t)(k0 + row) * N + n0 + nc * 8));
            }
        }
    };

    float acc[2][8][4];
#pragma unroll
    for (int i = 0; i < 2; i++)
#pragma unroll
        for (int j = 0; j < 8; j++)
#pragma unroll
            for (int t = 0; t < 4; t++) acc[i][j][t] = 0.f;

    load_stage(0); CP_COMMIT();
    load_stage(1); CP_COMMIT();

    const int lr = lane & 15;
    const int lc = lane >> 4;
    for (int s = 0; s < NST; s++) {
        if (s + 1 < NST) { CP_WAIT(1); } else { CP_WAIT(0); }
        __syncthreads();
        const uint32_t buf = sb + (uint32_t)(s % 3) * GSTAGE;
#pragma unroll
        for (int ks = 0; ks < 2; ks++) {
            uint32_t ah[2][4];
#pragma unroll
            for (int mi = 0; mi < 2; mi++)
                ldsm_x4(ah[mi], buf + (uint32_t)((wm * 32 + mi * 16 + lr) * 80 + ks * 32 + lc * 16));
            uint32_t bh[8][2];
#pragma unroll
            for (int nio = 0; nio < 4; nio++) {
                uint32_t addr = buf + GOFF_B +
                    (uint32_t)((ks * 16 + lr) * 272 + wn * 128 + nio * 32 + lc * 16);
                uint32_t t4[4];
                ldsm_x4_t(t4, addr);
                bh[nio * 2][0] = t4[0]; bh[nio * 2][1] = t4[1];
                bh[nio * 2 + 1][0] = t4[2]; bh[nio * 2 + 1][1] = t4[3];
            }
#pragma unroll
            for (int mi = 0; mi < 2; mi++)
#pragma unroll
                for (int ni = 0; ni < 8; ni++)
                    mma_f16(acc[mi][ni], ah[mi], bh[ni]);
        }
        if (s + 2 < NST) { load_stage(s + 2); CP_COMMIT(); }
    }

    const int gid = lane >> 2, tig = lane & 3;
    const int b_idx = GATE ? (m0 / rows_per_batch) : 0;
#pragma unroll
    for (int mi = 0; mi < 2; mi++) {
        int r = m0 + wm * 32 + mi * 16 + gid;
#pragma unroll
        for (int ni = 0; ni < 8; ni++) {
            int c = n0 + wn * 64 + ni * 8 + tig * 2;
            float g0 = 1.f, g1 = 1.f;
            if (GATE) {
                g0 = gate[b_idx * DMODEL + (c & (DMODEL - 1))];
                g1 = gate[b_idx * DMODEL + ((c + 1) & (DMODEL - 1))];
            }
            float bz0 = bias[c], bz1 = bias[c + 1];
            store_pair(&C[(size_t)r * N + c],
                       fmaxf(acc[mi][ni][0] + bz0, 0.f) * g0,
                       fmaxf(acc[mi][ni][1] + bz1, 0.f) * g1);
            store_pair(&C[(size_t)(r + 8) * N + c],
                       fmaxf(acc[mi][ni][2] + bz0, 0.f) * g0,
                       fmaxf(acc[mi][ni][3] + bz1, 0.f) * g1);
        }
    }
}

// ---------------------------------------------------------------------------
// fp16 tensor-core attention with fused residual epilogue.
// Block: 32 q-rows x (b,h). 128 threads, 4 warps.
// Writes out_h = half(resid + attn_out) — feeds the output projection.
// ---------------------------------------------------------------------------
template <int NK, int NROWS>
__global__ __launch_bounds__(128)
void attn16(const __half* __restrict__ tran, const float* __restrict__ resid,
            __half* __restrict__ outh) {
    constexpr int NC = NK / 64;
    constexpr int QSB = 272;
    constexpr int PSH = NK + 8;
    constexpr int OFF_KVB = 32 * QSB;
    constexpr int KVBUF = 64 * QSB;
    constexpr int OFF_PSB = OFF_KVB + 2 * KVBUF;
    constexpr int OFF_RINV = OFF_PSB + 32 * PSH * 2;

    extern __shared__ __align__(16) char smem[];
    const uint32_t sb = smem_u32(smem);
    __half* smh = (__half*)smem;
    float* rinv = (float*)(smem + OFF_RINV);

    const int tid = threadIdx.x;
    const int wid = tid >> 5, lane = tid & 31;
    const int lr = lane & 15, lc = lane >> 4;
    const int gid = lane >> 2, tig = lane & 3;
    const int q0 = blockIdx.x * 32, h = blockIdx.y, b = blockIdx.z;

    auto ldQ = [&]() {
#pragma unroll
        for (int i = 0; i < 4; i++) {
            int c = tid + i * 128;
            int row = c >> 4, ch = c & 15;
            cp_async16(sb + (uint32_t)(row * QSB + ch * 16),
                       tran + ((size_t)(b * NROWS + q0 + row) * D3 + DMODEL + h * DH + ch * 8));
        }
    };
    auto ldKV = [&](int part, int chunk, int buf) {
#pragma unroll
        for (int i = 0; i < 8; i++) {
            int c = tid + i * 128;
            int row = c >> 4, ch = c & 15;
            cp_async16(sb + OFF_KVB + (uint32_t)(buf * KVBUF + row * QSB + ch * 16),
                       tran + ((size_t)(b * NROWS + chunk * 64 + row) * D3 + part + h * DH + ch * 8));
        }
    };

    // ---------------- phase 1: logits ----------------
    ldQ(); ldKV(0, 0, 0); CP_COMMIT();
    for (int c = 0; c < NC; c++) {
        if (c + 1 < NC) { ldKV(0, c + 1, (c + 1) & 1); CP_COMMIT(); CP_WAIT(1); }
        else           { CP_WAIT(0); }
        __syncthreads();
        const uint32_t kb = sb + OFF_KVB + (uint32_t)((c & 1) * KVBUF);
        float acc[2][2][4];
#pragma unroll
        for (int mi = 0; mi < 2; mi++)
#pragma unroll
            for (int ni = 0; ni < 2; ni++)
#pragma unroll
                for (int t = 0; t < 4; t++) acc[mi][ni][t] = 0.f;
#pragma unroll
        for (int ks = 0; ks < 8; ks++) {
            uint32_t a[2][4];
            ldsm_x4(a[0], sb + (uint32_t)(lr * QSB + ks * 32 + lc * 16));
            ldsm_x4(a[1], sb + (uint32_t)((16 + lr) * QSB + ks * 32 + lc * 16));
            uint32_t r4[4];
            ldsm_x4(r4, kb + (uint32_t)((wid * 16 + lr) * QSB + ks * 32 + lc * 16));
            uint32_t b0[2] = {r4[0], r4[2]}, b1[2] = {r4[1], r4[3]};
            mma_f16(acc[0][0], a[0], b0); mma_f16(acc[0][1], a[0], b1);
            mma_f16(acc[1][0], a[1], b0); mma_f16(acc[1][1], a[1], b1);
        }
        const float scl = 0.08838834764831845f;   // 1/sqrt(128)
#pragma unroll
        for (int mi = 0; mi < 2; mi++)
#pragma unroll
            for (int ni = 0; ni < 2; ni++) {
                int col = c * 64 + wid * 16 + ni * 8 + tig * 2;
                *(__half2*)(smh + (OFF_PSB / 2) + (mi * 16 + gid) * PSH + col) =
                    __floats2half2_rn(acc[mi][ni][0] * scl, acc[mi][ni][1] * scl);
                *(__half2*)(smh + (OFF_PSB / 2) + (mi * 16 + gid + 8) * PSH + col) =
                    __floats2half2_rn(acc[mi][ni][2] * scl, acc[mi][ni][3] * scl);
            }
        __syncthreads();
    }

    // kick off V chunk 0 (overlaps softmax)
    ldKV(2 * DMODEL, 0, 0); CP_COMMIT();

    // ---------------- phase 2: softmax ----------------
    {
        const int row = tid >> 2, g = tid & 3;
        __half2* pr = (__half2*)(smh + (OFF_PSB / 2) + row * PSH);
        float m = -1e30f;
        for (int i = g; i < NK / 2; i += 4) {
            float2 f = __half22float2(pr[i]);
            m = fmaxf(m, fmaxf(f.x, f.y));
        }
        m = fmaxf(m, __shfl_xor_sync(0xffffffffu, m, 1));
        m = fmaxf(m, __shfl_xor_sync(0xffffffffu, m, 2));
        float s = 0.f;
        for (int i = g; i < NK / 2; i += 4) {
            float2 f = __half22float2(pr[i]);
            float e0 = __expf(f.x - m), e1 = __expf(f.y - m);
            s += e0 + e1;
            pr[i] = __floats2half2_rn(e0, e1);
        }
        s += __shfl_xor_sync(0xffffffffu, s, 1);
        s += __shfl_xor_sync(0xffffffffu, s, 2);
        if (g == 0) rinv[row] = 1.0f / s;
    }

    // ---------------- phase 3: O = P @ V ----------------
    float acc[2][4][4];
#pragma unroll
    for (int mi = 0; mi < 2; mi++)
#pragma unroll
        for (int ni = 0; ni < 4; ni++)
#pragma unroll
            for (int t = 0; t < 4; t++) acc[mi][ni][t] = 0.f;

    for (int c = 0; c < NC; c++) {
        if (c + 1 < NC) { ldKV(2 * DMODEL, c + 1, (c + 1) & 1); CP_COMMIT(); CP_WAIT(1); }
        else           { CP_WAIT(0); }
        __syncthreads();
        const uint32_t kb = sb + OFF_KVB + (uint32_t)((c & 1) * KVBUF);
#pragma unroll
        for (int ks = 0; ks < 4; ks++) {
            uint32_t a[2][4];
            ldsm_x4(a[0], sb + OFF_PSB + (uint32_t)(lr * PSH * 2 + (c * 64 + ks * 16 + lc * 8) * 2));
            ldsm_x4(a[1], sb + OFF_PSB + (uint32_t)((16 + lr) * PSH * 2 + (c * 64 + ks * 16 + lc * 8) * 2));
            uint32_t bv[4][2];
#pragma unroll
            for (int nio = 0; nio < 2; nio++) {
                uint32_t t4[4];
                ldsm_x4_t(t4, kb + (uint32_t)((ks * 16 + lr) * QSB + wid * 64 + nio * 32 + lc * 16));
                bv[nio * 2][0] = t4[0]; bv[nio * 2][1] = t4[1];
                bv[nio * 2 + 1][0] = t4[2]; bv[nio * 2 + 1][1] = t4[3];
            }
#pragma unroll
            for (int mi = 0; mi < 2; mi++)
#pragma unroll
                for (int ni = 0; ni < 4; ni++)
                    mma_f16(acc[mi][ni], a[mi], bv[ni]);
        }
        __syncthreads();
    }

    // epilogue: normalize, add residual, write fp16 (feeds output projection)
#pragma unroll
    for (int mi = 0; mi < 2; mi++) {
        int r0 = mi * 16 + gid, r1 = r0 + 8;
        float inv0 = rinv[r0], inv1 = rinv[r1];
#pragma unroll
        for (int ni = 0; ni < 4; ni++) {
            int col = h * DH + wid * 32 + ni * 8 + tig * 2;
            size_t i0 = (size_t)(b * NROWS + q0 + r0) * DMODEL + col;
            size_t i1 = (size_t)(b * NROWS + q0 + r1) * DMODEL + col;
            float2 rv0 = *(const float2*)&resid[i0];
            float2 rv1 = *(const float2*)&resid[i1];
            *(__half2*)&outh[i0] =
                __floats2half2_rn(acc[mi][ni][0] * inv0 + rv0.x, acc[mi][ni][1] * inv0 + rv0.y);
            *(__half2*)&outh[i1] =
                __floats2half2_rn(acc[mi][ni][2] * inv1 + rv1.x, acc[mi][ni][3] * inv1 + rv1.y);
        }
    }
}

// ---------------------------------------------------------------------------
// launch
// ---------------------------------------------------------------------------
extern "C" void kernel_launch(void* const* d_in, const int* in_sizes, int n_in,
                              void* d_out, int out_size) {
    const float* v      = (const float*)d_in[0];
    const float* q      = (const float*)d_in[1];
    const float* w_v4q  = (const float*)d_in[2];
    const float* b_v4q  = (const float*)d_in[3];
    const float* w_q4v  = (const float*)d_in[4];
    const float* b_q4v  = (const float*)d_in[5];
    const float* w_vlin = (const float*)d_in[6];
    const float* b_vlin = (const float*)d_in[7];
    const float* w_qlin = (const float*)d_in[8];
    const float* b_qlin = (const float*)d_in[9];
    const float* w_vout = (const float*)d_in[10];
    const float* b_vout = (const float*)d_in[11];
    const float* w_qout = (const float*)d_in[12];
    const float* b_qout = (const float*)d_in[13];

    float* out_v = (float*)d_out;
    float* out_q = out_v + (size_t)BATCH * NV * DMODEL;

    float *p_vmean, *p_qmean, *p_gv, *p_gq;
    cudaGetSymbolAddress((void**)&p_vmean, g_vmean);
    cudaGetSymbolAddress((void**)&p_qmean, g_qmean);
    cudaGetSymbolAddress((void**)&p_gv,    g_gate_v);
    cudaGetSymbolAddress((void**)&p_gq,    g_gate_q);

    __half *vtran, *qtran, *Av, *Aq, *Wvl, *Wql, *Wvo, *Wqo;
    cudaGetSymbolAddress((void**)&vtran, g_vtran_h);
    cudaGetSymbolAddress((void**)&qtran, g_qtran_h);
    cudaGetSymbolAddress((void**)&Av, g_Av);
    cudaGetSymbolAddress((void**)&Aq, g_Aq);
    cudaGetSymbolAddress((void**)&Wvl, g_Wvl);
    cudaGetSymbolAddress((void**)&Wql, g_Wql);
    cudaGetSymbolAddress((void**)&Wvo, g_Wvo);
    cudaGetSymbolAddress((void**)&Wqo, g_Wqo);

    const int SMEM_G = 3 * GSTAGE;
    cudaFuncSetAttribute((const void*)bmma_gemm<true, __half>, cudaFuncAttributeMaxDynamicSharedMemorySize, SMEM_G);
    cudaFuncSetAttribute((const void*)bmma_gemm<false, float>, cudaFuncAttributeMaxDynamicSharedMemorySize, SMEM_G);

    const int SMEM_AV = (32 * 272) + 2 * (64 * 272) + 32 * (512 + 8) * 2 + 128;
    const int SMEM_AQ = (32 * 272) + 2 * (64 * 272) + 32 * (256 + 8) * 2 + 128;
    cudaFuncSetAttribute((const void*)attn16<512, NV>, cudaFuncAttributeMaxDynamicSharedMemorySize, SMEM_AV);
    cudaFuncSetAttribute((const void*)attn16<256, NQ>, cudaFuncAttributeMaxDynamicSharedMemorySize, SMEM_AQ);

    // means + gates
    mean_kernel<<<dim3(BATCH, 4), 256>>>(v, p_vmean, NV);
    mean_kernel<<<dim3(BATCH, 4), 256>>>(q, p_qmean, NQ);
    gate_kernel<<<dim3(BATCH, 8), 512>>>(p_vmean, w_v4q, b_v4q, p_gq);
    gate_kernel<<<dim3(BATCH, 8), 512>>>(p_qmean, w_q4v, b_q4v, p_gv);

    // operand conversions (single fp16)
    const int nAv = BATCH * NV * DMODEL, nAq = BATCH * NQ * DMODEL;
    const int nWl = DMODEL * D3, nWo = DMODEL * DMODEL;
    tohalf_kernel<<<nAv / 1024, 256>>>(v, Av, nAv);
    tohalf_kernel<<<nAq / 1024, 256>>>(q, Aq, nAq);
    tohalf_kernel<<<nWl / 1024, 256>>>(w_vlin, Wvl, nWl);
    tohalf_kernel<<<nWl / 1024, 256>>>(w_qlin, Wql, nWl);
    tohalf_kernel<<<nWo / 1024, 256>>>(w_vout, Wvo, nWo);
    tohalf_kernel<<<nWo / 1024, 256>>>(w_qout, Wqo, nWo);

    // gated tran projections -> fp16 tran
    bmma_gemm<true, __half><<<dim3(D3 / 128, BATCH * NV / 128), 256, SMEM_G>>>(
        Av, Wvl, b_vlin, p_gv, vtran, BATCH * NV, D3, DMODEL, NV);
    bmma_gemm<true, __half><<<dim3(D3 / 128, BATCH * NQ / 128), 256, SMEM_G>>>(
        Aq, Wql, b_qlin, p_gq, qtran, BATCH * NQ, D3, DMODEL, NQ);

    // tensor-core attention with fused residual (overwrites Av/Aq with half(v + upd))
    attn16<512, NV><<<dim3(NV / 32, NHEAD, BATCH), 128, SMEM_AV>>>(vtran, v, Av);
    attn16<256, NQ><<<dim3(NQ / 32, NHEAD, BATCH), 128, SMEM_AQ>>>(qtran, q, Aq);

    // output projections
    bmma_gemm<false, float><<<dim3(DMODEL / 128, BATCH * NV / 128), 256, SMEM_G>>>(
        Av, Wvo, b_vout, nullptr, out_v, BATCH * NV, DMODEL, DMODEL, NV);
    bmma_gemm<false, float><<<dim3(DMODEL / 128, BATCH * NQ / 128), 256, SMEM_G>>>(
        Aq, Wqo, b_qout, nullptr, out_q, BATCH * NQ, DMODEL, DMODEL, NQ);
}

// round 11
// speedup vs baseline: 11.8315x; 1.0504x over previous
#include <cuda_runtime.h>
#include <cuda_fp16.h>
#include <math.h>
#include <stdint.h>

// Problem constants
#define BATCH 32
#define NV    512
#define NQ    256
#define DMODEL 1024
#define D3    3072
#define NHEAD 8
#define DH    128

// ---------------------------------------------------------------------------
// Scratch (static device globals — allocation-free per harness rules)
// ---------------------------------------------------------------------------
__device__ float g_vmean[BATCH * DMODEL];
__device__ float g_qmean[BATCH * DMODEL];
__device__ float g_gate_v[BATCH * DMODEL];
__device__ float g_gate_q[BATCH * DMODEL];
__device__ __half g_vtran_h[BATCH * NV * D3];
__device__ __half g_qtran_h[BATCH * NQ * D3];
__device__ __half g_Av[BATCH * NV * DMODEL];   // half(v), then half(v+upd)
__device__ __half g_Aq[BATCH * NQ * DMODEL];
__device__ __half g_Wvl[DMODEL * D3];
__device__ __half g_Wql[DMODEL * D3];
__device__ __half g_Wvo[DMODEL * DMODEL];
__device__ __half g_Wqo[DMODEL * DMODEL];

// ---------------------------------------------------------------------------
// PTX helpers
// ---------------------------------------------------------------------------
__device__ __forceinline__ uint32_t smem_u32(const void* p) {
    uint32_t a;
    asm("{ .reg .u64 t; cvta.to.shared.u64 t, %1; cvt.u32.u64 %0, t; }" : "=r"(a) : "l"(p));
    return a;
}
__device__ __forceinline__ void cp_async16(uint32_t dst, const void* src) {
    asm volatile("cp.async.cg.shared.global [%0], [%1], 16;" :: "r"(dst), "l"(src));
}
#define CP_COMMIT() asm volatile("cp.async.commit_group;" ::: "memory")
#define CP_WAIT(n)  asm volatile("cp.async.wait_group %0;" :: "n"(n) : "memory")

__device__ __forceinline__ void ldsm_x4(uint32_t* d, uint32_t addr) {
    asm volatile("ldmatrix.sync.aligned.m8n8.x4.shared.b16 {%0,%1,%2,%3}, [%4];"
                 : "=r"(d[0]), "=r"(d[1]), "=r"(d[2]), "=r"(d[3]) : "r"(addr));
}
__device__ __forceinline__ void ldsm_x4_t(uint32_t* d, uint32_t addr) {
    asm volatile("ldmatrix.sync.aligned.m8n8.x4.trans.shared.b16 {%0,%1,%2,%3}, [%4];"
                 : "=r"(d[0]), "=r"(d[1]), "=r"(d[2]), "=r"(d[3]) : "r"(addr));
}
__device__ __forceinline__ void mma_f16(float* c, const uint32_t* a, const uint32_t* b) {
    asm volatile(
        "mma.sync.aligned.m16n8k16.row.col.f32.f16.f16.f32 "
        "{%0,%1,%2,%3}, {%4,%5,%6,%7}, {%8,%9}, {%0,%1,%2,%3};"
        : "+f"(c[0]), "+f"(c[1]), "+f"(c[2]), "+f"(c[3])
        : "r"(a[0]), "r"(a[1]), "r"(a[2]), "r"(a[3]), "r"(b[0]), "r"(b[1]));
}

__device__ __forceinline__ void store_pair(float* p, float x, float y) {
    *(float2*)p = make_float2(x, y);
}
__device__ __forceinline__ void store_pair(__half* p, float x, float y) {
    *(__half2*)p = __floats2half2_rn(x, y);
}

// ---------------------------------------------------------------------------
// Combined means: grid (BATCH, 4, 2); z=0 -> v (512 rows), z=1 -> q (256 rows)
// ---------------------------------------------------------------------------
__global__ void mean2_kernel(const float* __restrict__ v, const float* __restrict__ q,
                             float* __restrict__ outv, float* __restrict__ outq) {
    const int z = blockIdx.z;
    const float* x = z ? q : v;
    float* out    = z ? outq : outv;
    const int nrows = z ? NQ : NV;
    int b = blockIdx.x;
    int d = blockIdx.y * 256 + threadIdx.x;
    const float* p = x + (size_t)b * nrows * DMODEL + d;
    float s0 = 0.f, s1 = 0.f, s2 = 0.f, s3 = 0.f;
    for (int n = 0; n < nrows; n += 4) {
        s0 += p[(size_t)(n + 0) * DMODEL];
        s1 += p[(size_t)(n + 1) * DMODEL];
        s2 += p[(size_t)(n + 2) * DMODEL];
        s3 += p[(size_t)(n + 3) * DMODEL];
    }
    out[b * DMODEL + d] = (s0 + s1 + s2 + s3) / (float)nrows;
}

// ---------------------------------------------------------------------------
// Prologue2: one launch doing BOTH gates (blocks 0..511) and ALL six
// fp32->fp16 conversions (blocks 512..8703). 512 threads/block.
// Conversion regions in 8-element units.
// ---------------------------------------------------------------------------
#define U_AV  (BATCH * NV * DMODEL / 8)        // 2097152
#define U_AQ  (BATCH * NQ * DMODEL / 8)        // 1048576
#define U_WL  (DMODEL * D3 / 8)                // 393216
#define U_WO  (DMODEL * DMODEL / 8)            // 131072
#define UC1  (U_AV)
#define UC2  (UC1 + U_AQ)
#define UC3  (UC2 + U_WL)
#define UC4  (UC3 + U_WL)
#define UC5  (UC4 + U_WO)
#define UC6  (UC5 + U_WO)                      // 4194304 total -> 8192 blocks
#define PRO_BLOCKS (512 + UC6 / 512)

__device__ __forceinline__ void conv8(const float* __restrict__ x, __half* __restrict__ y, size_t i) {
    float4 a = *(const float4*)(x + i);
    float4 b = *(const float4*)(x + i + 4);
    __half2 h[4];
    h[0] = __floats2half2_rn(a.x, a.y);
    h[1] = __floats2half2_rn(a.z, a.w);
    h[2] = __floats2half2_rn(b.x, b.y);
    h[3] = __floats2half2_rn(b.z, b.w);
    *(uint4*)(y + i) = *(uint4*)h;
}

__global__ __launch_bounds__(512)
void prologue2(const float* __restrict__ mean_v, const float* __restrict__ mean_q,
               const float* __restrict__ w_v4q, const float* __restrict__ b_v4q,
               const float* __restrict__ w_q4v, const float* __restrict__ b_q4v,
               float* __restrict__ gate_q, float* __restrict__ gate_v,
               const float* __restrict__ v, const float* __restrict__ q,
               const float* __restrict__ wvl, const float* __restrict__ wql,
               const float* __restrict__ wvo, const float* __restrict__ wqo,
               __half* __restrict__ Av, __half* __restrict__ Aq,
               __half* __restrict__ Wvl, __half* __restrict__ Wql,
               __half* __restrict__ Wvo, __half* __restrict__ Wqo) {
    const int blk = blockIdx.x;
    if (blk < 512) {
        // -------- gate part --------
        const int side = blk >> 8;                 // 0: v_mean -> gate_q ; 1: q_mean -> gate_v
        const int rem = blk & 255;
        const int b = rem & 31;
        const int dcol = rem >> 5;
        const float* mean = side ? mean_q : mean_v;
        const float* W    = side ? w_q4v : w_v4q;
        const float* bias = side ? b_q4v : b_v4q;
        float* gate       = side ? gate_v : gate_q;

        __shared__ float sm[DMODEL];
        __shared__ float part[4][128];
        const int l = threadIdx.x & 127;
        const int ks = threadIdx.x >> 7;
        const int d = dcol * 128 + l;
        for (int i = threadIdx.x; i < DMODEL; i += 512) sm[i] = mean[b * DMODEL + i];
        __syncthreads();
        const int k0 = ks * 256;
        float a0 = 0.f, a1 = 0.f, a2 = 0.f, a3 = 0.f;
#pragma unroll 4
        for (int k = 0; k < 256; k += 4) {
            a0 += sm[k0 + k + 0] * __ldg(&W[(size_t)(k0 + k + 0) * DMODEL + d]);
            a1 += sm[k0 + k + 1] * __ldg(&W[(size_t)(k0 + k + 1) * DMODEL + d]);
            a2 += sm[k0 + k + 2] * __ldg(&W[(size_t)(k0 + k + 2) * DMODEL + d]);
            a3 += sm[k0 + k + 3] * __ldg(&W[(size_t)(k0 + k + 3) * DMODEL + d]);
        }
        part[ks][l] = (a0 + a1) + (a2 + a3);
        __syncthreads();
        if (ks == 0) {
            float acc = part[0][l] + part[1][l] + part[2][l] + part[3][l] + bias[d];
            gate[b * DMODEL + d] = 1.0f + 1.0f / (1.0f + __expf(-acc));
        }
    } else {
        // -------- conversion part: 8-elem unit per thread --------
        const int u = (blk - 512) * 512 + threadIdx.x;
        if (u < UC1)      conv8(v,   Av,  (size_t)u * 8);
        else if (u < UC2) conv8(q,   Aq,  (size_t)(u - UC1) * 8);
        else if (u < UC3) conv8(wvl, Wvl, (size_t)(u - UC2) * 8);
        else if (u < UC4) conv8(wql, Wql, (size_t)(u - UC3) * 8);
        else if (u < UC5) conv8(wvo, Wvo, (size_t)(u - UC4) * 8);
        else              conv8(wqo, Wqo, (size_t)(u - UC5) * 8);
    }
}

// ---------------------------------------------------------------------------
// Merged two-sided fp16 mma GEMM.  grid.y in [0, MBv + MBq):
//   by <  MBv : v side (m0 = by*128)
//   by >= MBv : q side (m0 = (by-MBv)*128)
// CTA 128x128, BK=32, 256 threads, warp tile 32x64, 3-stage cp.async pipeline.
// ---------------------------------------------------------------------------
#define GSTAGE 18944
#define GOFF_B 10240
#define MBV (BATCH * NV / 128)    // 128
#define MBQ (BATCH * NQ / 128)    // 64

template <bool GATE, typename OUT>
__global__ __launch_bounds__(256)
void bmma_gemm2(const __half* __restrict__ Avp, const __half* __restrict__ Bvp,
                const float* __restrict__ biasv, const float* __restrict__ gatev,
                OUT* __restrict__ Cvp,
                const __half* __restrict__ Aqp, const __half* __restrict__ Bqp,
                const float* __restrict__ biasq, const float* __restrict__ gateq,
                OUT* __restrict__ Cqp,
                int N, int K) {
    extern __shared__ __align__(16) char smem[];
    const uint32_t sb = smem_u32(smem);
    const int tid = threadIdx.x;
    const int warp = tid >> 5, lane = tid & 31;
    const int wm = warp & 3, wn = warp >> 2;

    const int by = blockIdx.y;
    const bool qside = (by >= MBV);
    const __half* A = qside ? Aqp : Avp;
    const __half* B = qside ? Bqp : Bvp;
    const float* bias = qside ? biasq : biasv;
    const float* gate = qside ? gateq : gatev;
    OUT* C = qside ? Cqp : Cvp;
    const int rpb = qside ? NQ : NV;
    const int m0 = (qside ? by - MBV : by) * 128;
    const int n0 = blockIdx.x * 128;
    const int NST = K >> 5;

    auto load_stage = [&](int s) {
        const uint32_t buf = sb + (uint32_t)(s % 3) * GSTAGE;
        const int k0 = s * 32;
#pragma unroll
        for (int i = 0; i < 2; i++) {
            int c = tid + i * 256;
            {
                int row = c >> 2, kc = c & 3;
                cp_async16(buf + (uint32_t)(row * 80 + kc * 16),
                           A + ((size_t)(m0 + row) * K + k0 + kc * 8));
            }
            {
                int row = c >> 4, nc = c & 15;
                cp_async16(buf + GOFF_B + (uint32_t)(row * 272 + nc * 16),
                           B + ((size_t)(k0 + row) * N + n0 + nc * 8));
            }
        }
    };

    float acc[2][8][4];
#pragma unroll
    for (int i = 0; i < 2; i++)
#pragma unroll
        for (int j = 0; j < 8; j++)
#pragma unroll
            for (int t = 0; t < 4; t++) acc[i][j][t] = 0.f;

    load_stage(0); CP_COMMIT();
    load_stage(1); CP_COMMIT();

    const int lr = lane & 15;
    const int lc = lane >> 4;
    for (int s = 0; s < NST; s++) {
        if (s + 1 < NST) { CP_WAIT(1); } else { CP_WAIT(0); }
        __syncthreads();
        const uint32_t buf = sb + (uint32_t)(s % 3) * GSTAGE;
#pragma unroll
        for (int ks = 0; ks < 2; ks++) {
            uint32_t ah[2][4];
#pragma unroll
            for (int mi = 0; mi < 2; mi++)
                ldsm_x4(ah[mi], buf + (uint32_t)((wm * 32 + mi * 16 + lr) * 80 + ks * 32 + lc * 16));
            uint32_t bh[8][2];
#pragma unroll
            for (int nio = 0; nio < 4; nio++) {
                uint32_t addr = buf + GOFF_B +
                    (uint32_t)((ks * 16 + lr) * 272 + wn * 128 + nio * 32 + lc * 16);
                uint32_t t4[4];
                ldsm_x4_t(t4, addr);
                bh[nio * 2][0] = t4[0]; bh[nio * 2][1] = t4[1];
                bh[nio * 2 + 1][0] = t4[2]; bh[nio * 2 + 1][1] = t4[3];
            }
#pragma unroll
            for (int mi = 0; mi < 2; mi++)
#pragma unroll
                for (int ni = 0; ni < 8; ni++)
                    mma_f16(acc[mi][ni], ah[mi], bh[ni]);
        }
        if (s + 2 < NST) { load_stage(s + 2); CP_COMMIT(); }
    }

    const int gid = lane >> 2, tig = lane & 3;
    const int b_idx = GATE ? (m0 / rpb) : 0;
#pragma unroll
    for (int mi = 0; mi < 2; mi++) {
        int r = m0 + wm * 32 + mi * 16 + gid;
#pragma unroll
        for (int ni = 0; ni < 8; ni++) {
            int c = n0 + wn * 64 + ni * 8 + tig * 2;
            float g0 = 1.f, g1 = 1.f;
            if (GATE) {
                g0 = gate[b_idx * DMODEL + (c & (DMODEL - 1))];
                g1 = gate[b_idx * DMODEL + ((c + 1) & (DMODEL - 1))];
            }
            float bz0 = bias[c], bz1 = bias[c + 1];
            store_pair(&C[(size_t)r * N + c],
                       fmaxf(acc[mi][ni][0] + bz0, 0.f) * g0,
                       fmaxf(acc[mi][ni][1] + bz1, 0.f) * g1);
            store_pair(&C[(size_t)(r + 8) * N + c],
                       fmaxf(acc[mi][ni][2] + bz0, 0.f) * g0,
                       fmaxf(acc[mi][ni][3] + bz1, 0.f) * g1);
        }
    }
}

// ---------------------------------------------------------------------------
// Merged fp16 tensor-core attention with fused residual epilogue.
// grid (16, NHEAD, 64): z<32 -> v side (NK=512), z>=32 -> q side (NK=256,
// blocks with x>=8 exit). 128 threads, 4 warps, 32 q-rows per block.
// ---------------------------------------------------------------------------
#define QSB  272
#define PSH  520                                  // logits stride (halves), both sides
#define OFF_KVB (32 * QSB)                        // 8704
#define KVBUF   (64 * QSB)                        // 17408
#define OFF_PSB (OFF_KVB + 2 * KVBUF)             // 43520
#define OFF_RINV (OFF_PSB + 32 * PSH * 2)         // 76800
#define SMEM_ATT (OFF_RINV + 128)                 // 76928

__global__ __launch_bounds__(128)
void attn16m(const __half* __restrict__ vtran, const float* __restrict__ vres,
             __half* __restrict__ vout,
             const __half* __restrict__ qtran, const float* __restrict__ qres,
             __half* __restrict__ qout) {
    const int z = blockIdx.z;
    const bool qsd = (z >= 32);
    if (qsd && blockIdx.x >= NQ / 32) return;
    const __half* tran = qsd ? qtran : vtran;
    const float* resid = qsd ? qres : vres;
    __half* outh       = qsd ? qout : vout;
    const int NK    = qsd ? NQ : NV;
    const int NROWS = NK;
    const int b     = qsd ? z - 32 : z;
    const int NC    = NK >> 6;

    extern __shared__ __align__(16) char smem[];
    const uint32_t sb = smem_u32(smem);
    __half* smh = (__half*)smem;
    float* rinv = (float*)(smem + OFF_RINV);

    const int tid = threadIdx.x;
    const int wid = tid >> 5, lane = tid & 31;
    const int lr = lane & 15, lc = lane >> 4;
    const int gid = lane >> 2, tig = lane & 3;
    const int q0 = blockIdx.x * 32, h = blockIdx.y;

    auto ldQ = [&]() {
#pragma unroll
        for (int i = 0; i < 4; i++) {
            int c = tid + i * 128;
            int row = c >> 4, ch = c & 15;
            cp_async16(sb + (uint32_t)(row * QSB + ch * 16),
                       tran + ((size_t)(b * NROWS + q0 + row) * D3 + DMODEL + h * DH + ch * 8));
        }
    };
    auto ldKV = [&](int part, int chunk, int buf) {
#pragma unroll
        for (int i = 0; i < 8; i++) {
            int c = tid + i * 128;
            int row = c >> 4, ch = c & 15;
            cp_async16(sb + OFF_KVB + (uint32_t)(buf * KVBUF + row * QSB + ch * 16),
                       tran + ((size_t)(b * NROWS + chunk * 64 + row) * D3 + part + h * DH + ch * 8));
        }
    };

    // ---------------- phase 1: logits ----------------
    ldQ(); ldKV(0, 0, 0); CP_COMMIT();
    for (int c = 0; c < NC; c++) {
        if (c + 1 < NC) { ldKV(0, c + 1, (c + 1) & 1); CP_COMMIT(); CP_WAIT(1); }
        else           { CP_WAIT(0); }
        __syncthreads();
        const uint32_t kb = sb + OFF_KVB + (uint32_t)((c & 1) * KVBUF);
        float acc[2][2][4];
#pragma unroll
        for (int mi = 0; mi < 2; mi++)
#pragma unroll
            for (int ni = 0; ni < 2; ni++)
#pragma unroll
                for (int t = 0; t < 4; t++) acc[mi][ni][t] = 0.f;
#pragma unroll
        for (int ks = 0; ks < 8; ks++) {
            uint32_t a[2][4];
            ldsm_x4(a[0], sb + (uint32_t)(lr * QSB + ks * 32 + lc * 16));
            ldsm_x4(a[1], sb + (uint32_t)((16 + lr) * QSB + ks * 32 + lc * 16));
            uint32_t r4[4];
            ldsm_x4(r4, kb + (uint32_t)((wid * 16 + lr) * QSB + ks * 32 + lc * 16));
            uint32_t b0[2] = {r4[0], r4[2]}, b1[2] = {r4[1], r4[3]};
            mma_f16(acc[0][0], a[0], b0); mma_f16(acc[0][1], a[0], b1);
            mma_f16(acc[1][0], a[1], b0); mma_f16(acc[1][1], a[1], b1);
        }
        const float scl = 0.08838834764831845f;   // 1/sqrt(128)
#pragma unroll
        for (int mi = 0; mi < 2; mi++)
#pragma unroll
            for (int ni = 0; ni < 2; ni++) {
                int col = c * 64 + wid * 16 + ni * 8 + tig * 2;
                *(__half2*)(smh + (OFF_PSB / 2) + (mi * 16 + gid) * PSH + col) =
                    __floats2half2_rn(acc[mi][ni][0] * scl, acc[mi][ni][1] * scl);
                *(__half2*)(smh + (OFF_PSB / 2) + (mi * 16 + gid + 8) * PSH + col) =
                    __floats2half2_rn(acc[mi][ni][2] * scl, acc[mi][ni][3] * scl);
            }
        __syncthreads();
    }

    // kick off V chunk 0 (overlaps softmax)
    ldKV(2 * DMODEL, 0, 0); CP_COMMIT();

    // ---------------- phase 2: softmax ----------------
    {
        const int row = tid >> 2, g = tid & 3;
        __half2* pr = (__half2*)(smh + (OFF_PSB / 2) + row * PSH);
        float m = -1e30f;
        for (int i = g; i < NK / 2; i += 4) {
            float2 f = __half22float2(pr[i]);
            m = fmaxf(m, fmaxf(f.x, f.y));
        }
        m = fmaxf(m, __shfl_xor_sync(0xffffffffu, m, 1));
        m = fmaxf(m, __shfl_xor_sync(0xffffffffu, m, 2));
        float s = 0.f;
        for (int i = g; i < NK / 2; i += 4) {
            float2 f = __half22float2(pr[i]);
            float e0 = __expf(f.x - m), e1 = __expf(f.y - m);
            s += e0 + e1;
            pr[i] = __floats2half2_rn(e0, e1);
        }
        s += __shfl_xor_sync(0xffffffffu, s, 1);
        s += __shfl_xor_sync(0xffffffffu, s, 2);
        if (g == 0) rinv[row] = 1.0f / s;
    }

    // ---------------- phase 3: O = P @ V ----------------
    float acc[2][4][4];
#pragma unroll
    for (int mi = 0; mi < 2; mi++)
#pragma unroll
        for (int ni = 0; ni < 4; ni++)
#pragma unroll
            for (int t = 0; t < 4; t++) acc[mi][ni][t] = 0.f;

    for (int c = 0; c < NC; c++) {
        if (c + 1 < NC) { ldKV(2 * DMODEL, c + 1, (c + 1) & 1); CP_COMMIT(); CP_WAIT(1); }
        else           { CP_WAIT(0); }
        __syncthreads();
        const uint32_t kb = sb + OFF_KVB + (uint32_t)((c & 1) * KVBUF);
#pragma unroll
        for (int ks = 0; ks < 4; ks++) {
            uint32_t a[2][4];
            ldsm_x4(a[0], sb + OFF_PSB + (uint32_t)(lr * PSH * 2 + (c * 64 + ks * 16 + lc * 8) * 2));
            ldsm_x4(a[1], sb + OFF_PSB + (uint32_t)((16 + lr) * PSH * 2 + (c * 64 + ks * 16 + lc * 8) * 2));
            uint32_t bv[4][2];
#pragma unroll
            for (int nio = 0; nio < 2; nio++) {
                uint32_t t4[4];
                ldsm_x4_t(t4, kb + (uint32_t)((ks * 16 + lr) * QSB + wid * 64 + nio * 32 + lc * 16));
                bv[nio * 2][0] = t4[0]; bv[nio * 2][1] = t4[1];
                bv[nio * 2 + 1][0] = t4[2]; bv[nio * 2 + 1][1] = t4[3];
            }
#pragma unroll
            for (int mi = 0; mi < 2; mi++)
#pragma unroll
                for (int ni = 0; ni < 4; ni++)
                    mma_f16(acc[mi][ni], a[mi], bv[ni]);
        }
        __syncthreads();
    }

    // epilogue: normalize, add residual, write fp16 (feeds output projection)
#pragma unroll
    for (int mi = 0; mi < 2; mi++) {
        int r0 = mi * 16 + gid, r1 = r0 + 8;
        float inv0 = rinv[r0], inv1 = rinv[r1];
#pragma unroll
        for (int ni = 0; ni < 4; ni++) {
            int col = h * DH + wid * 32 + ni * 8 + tig * 2;
            size_t i0 = (size_t)(b * NROWS + q0 + r0) * DMODEL + col;
            size_t i1 = (size_t)(b * NROWS + q0 + r1) * DMODEL + col;
            float2 rv0 = *(const float2*)&resid[i0];
            float2 rv1 = *(const float2*)&resid[i1];
            *(__half2*)&outh[i0] =
                __floats2half2_rn(acc[mi][ni][0] * inv0 + rv0.x, acc[mi][ni][1] * inv0 + rv0.y);
            *(__half2*)&outh[i1] =
                __floats2half2_rn(acc[mi][ni][2] * inv1 + rv1.x, acc[mi][ni][3] * inv1 + rv1.y);
        }
    }
}

// ---------------------------------------------------------------------------
// launch — 5 kernels total
// ---------------------------------------------------------------------------
extern "C" void kernel_launch(void* const* d_in, const int* in_sizes, int n_in,
                              void* d_out, int out_size) {
    const float* v      = (const float*)d_in[0];
    const float* q      = (const float*)d_in[1];
    const float* w_v4q  = (const float*)d_in[2];
    const float* b_v4q  = (const float*)d_in[3];
    const float* w_q4v  = (const float*)d_in[4];
    const float* b_q4v  = (const float*)d_in[5];
    const float* w_vlin = (const float*)d_in[6];
    const float* b_vlin = (const float*)d_in[7];
    const float* w_qlin = (const float*)d_in[8];
    const float* b_qlin = (const float*)d_in[9];
    const float* w_vout = (const float*)d_in[10];
    const float* b_vout = (const float*)d_in[11];
    const float* w_qout = (const float*)d_in[12];
    const float* b_qout = (const float*)d_in[13];

    float* out_v = (float*)d_out;
    float* out_q = out_v + (size_t)BATCH * NV * DMODEL;

    float *p_vmean, *p_qmean, *p_gv, *p_gq;
    cudaGetSymbolAddress((void**)&p_vmean, g_vmean);
    cudaGetSymbolAddress((void**)&p_qmean, g_qmean);
    cudaGetSymbolAddress((void**)&p_gv,    g_gate_v);
    cudaGetSymbolAddress((void**)&p_gq,    g_gate_q);

    __half *vtran, *qtran, *Av, *Aq, *Wvl, *Wql, *Wvo, *Wqo;
    cudaGetSymbolAddress((void**)&vtran, g_vtran_h);
    cudaGetSymbolAddress((void**)&qtran, g_qtran_h);
    cudaGetSymbolAddress((void**)&Av, g_Av);
    cudaGetSymbolAddress((void**)&Aq, g_Aq);
    cudaGetSymbolAddress((void**)&Wvl, g_Wvl);
    cudaGetSymbolAddress((void**)&Wql, g_Wql);
    cudaGetSymbolAddress((void**)&Wvo, g_Wvo);
    cudaGetSymbolAddress((void**)&Wqo, g_Wqo);

    const int SMEM_G = 3 * GSTAGE;
    cudaFuncSetAttribute((const void*)bmma_gemm2<true, __half>, cudaFuncAttributeMaxDynamicSharedMemorySize, SMEM_G);
    cudaFuncSetAttribute((const void*)bmma_gemm2<false, float>, cudaFuncAttributeMaxDynamicSharedMemorySize, SMEM_G);
    cudaFuncSetAttribute((const void*)attn16m, cudaFuncAttributeMaxDynamicSharedMemorySize, SMEM_ATT);

    // 1) means (both sides)
    mean2_kernel<<<dim3(BATCH, 4, 2), 256>>>(v, q, p_vmean, p_qmean);

    // 2) gates + all conversions (one launch)
    prologue2<<<PRO_BLOCKS, 512>>>(p_vmean, p_qmean, w_v4q, b_v4q, w_q4v, b_q4v,
                                   p_gq, p_gv, v, q, w_vlin, w_qlin, w_vout, w_qout,
                                   Av, Aq, Wvl, Wql, Wvo, Wqo);

    // 3) gated tran projections (both sides, one launch) -> fp16 tran
    bmma_gemm2<true, __half><<<dim3(D3 / 128, MBV + MBQ), 256, SMEM_G>>>(
        Av, Wvl, b_vlin, p_gv, vtran,
        Aq, Wql, b_qlin, p_gq, qtran, D3, DMODEL);

    // 4) attention with fused residual (both sides, one launch)
    attn16m<<<dim3(NV / 32, NHEAD, 64), 128, SMEM_ATT>>>(vtran, v, Av, qtran, q, Aq);

    // 5) output projections (both sides, one launch)
    bmma_gemm2<false, float><<<dim3(DMODEL / 128, MBV + MBQ), 256, SMEM_G>>>(
        Av, Wvo, b_vout, nullptr, out_v,
        Aq, Wqo, b_qout, nullptr, out_q, DMODEL, DMODEL);
}